// round 1
// baseline (speedup 1.0000x reference)
#include <cuda_runtime.h>
#include <stdint.h>

// ---------------------------------------------------------------------------
// TCNN INR fused kernel: hash-grid encoding + MLP 48->128->128->1 (tf32 MMA)
// ---------------------------------------------------------------------------

#define NLEVELS 12
#define TBL (1u << 20)
#define IMG 1024

// smem strides (floats), chosen for bank-conflict-free mma fragment loads
#define XS_STRIDE 52     // A-frag addr (20g+c)%32 -> all distinct
#define H1_STRIDE 132    // A-frag addr (4g+c)%32  -> all distinct
#define W_STRIDE 136     // B-frag addr (8c+g)%32  -> all distinct

#define SMEM_FLOATS (128 * XS_STRIDE + 128 * H1_STRIDE + 48 * W_STRIDE + 128 * W_STRIDE + 128)
#define SMEM_BYTES (SMEM_FLOATS * 4)

#define TILES_PER_CTA 8
#define NCTA 1024   // 8192 tiles (64 x 128 of 16x8 pixels) / 8

// scale = 16*1.5^l - 1 (exact in fp32), res = ceil(scale)+1; levels 0..10 dense
__constant__ float c_scale[NLEVELS] = {
    15.0f, 23.0f, 35.0f, 53.0f, 80.0f, 120.5f, 181.25f, 272.375f,
    409.0625f, 614.09375f, 921.640625f, 1382.9609375f};
__constant__ int c_res[NLEVELS] = {16, 24, 36, 54, 81, 122, 183, 274, 411, 616, 923, 1384};

__device__ __forceinline__ float tf32r(float f) {
    uint32_t u;
    asm("cvt.rna.tf32.f32 %0, %1;" : "=r"(u) : "f"(f));
    return __uint_as_float(u);
}

__device__ __forceinline__ void mma8(float d[4], const float a[4], float b0f, float b1f) {
    uint32_t a0 = __float_as_uint(a[0]), a1 = __float_as_uint(a[1]);
    uint32_t a2 = __float_as_uint(a[2]), a3 = __float_as_uint(a[3]);
    uint32_t b0 = __float_as_uint(b0f), b1 = __float_as_uint(b1f);
    asm volatile(
        "mma.sync.aligned.m16n8k8.row.col.f32.tf32.tf32.f32 "
        "{%0,%1,%2,%3}, {%4,%5,%6,%7}, {%8,%9}, {%0,%1,%2,%3};"
        : "+f"(d[0]), "+f"(d[1]), "+f"(d[2]), "+f"(d[3])
        : "r"(a0), "r"(a1), "r"(a2), "r"(a3), "r"(b0), "r"(b1));
}

__global__ __launch_bounds__(256, 1) void inr_kernel(
    const float4* __restrict__ tab,   // [12][2^20] float4
    const float* __restrict__ w1,     // [48][128]
    const float* __restrict__ w2,     // [128][128]
    const float* __restrict__ w3,     // [128]
    float* __restrict__ out)          // [1024*1024]
{
    extern __shared__ float sm[];
    float* Xs  = sm;                        // [128][XS_STRIDE]  encoded features (tf32)
    float* H1s = Xs + 128 * XS_STRIDE;      // [128][H1_STRIDE]  relu(h1) (tf32)
    float* W1s = H1s + 128 * H1_STRIDE;     // [48][W_STRIDE]    w1 (tf32)
    float* W2s = W1s + 48 * W_STRIDE;       // [128][W_STRIDE]   w2 (tf32)
    float* w3s = W2s + 128 * W_STRIDE;      // [128]             w3 (fp32)

    const int tid = threadIdx.x;

    // -- stage weights once per CTA (converted to tf32) --
    for (int i = tid; i < 48 * 128; i += 256) {
        int k = i >> 7, n = i & 127;
        W1s[k * W_STRIDE + n] = tf32r(w1[i]);
    }
    for (int i = tid; i < 128 * 128; i += 256) {
        int k = i >> 7, n = i & 127;
        W2s[k * W_STRIDE + n] = tf32r(w2[i]);
    }
    if (tid < 128) w3s[tid] = w3[tid];
    __syncthreads();

    const int lane = tid & 31, wid = tid >> 5;
    const int g = lane >> 2, cq = lane & 3;   // mma group / thread-in-group
    const int m0 = wid << 4;                  // this warp owns rows m0..m0+15

    for (int it = 0; it < TILES_PER_CTA; ++it) {
        const int t = blockIdx.x * TILES_PER_CTA + it;
        const int tx = t & 63, ty = t >> 6;   // 16x8 pixel tile coords

        // ---------------- encoding: 2 threads per pixel (6 levels each) -----
        {
            const int r = m0 + (lane >> 1);
            const int gx = (tx << 4) + (r & 15);
            const int gy = (ty << 3) + (r >> 4);
            const float fx = (float)gx * (1.0f / 1023.0f);
            const float fy = (float)gy * (1.0f / 1023.0f);
            const int l0 = (lane & 1) * 6;
#pragma unroll
            for (int j = 0; j < 6; j++) {
                const int l = l0 + j;
                const float s = c_scale[l];
                const uint32_t R = (uint32_t)c_res[l];
                float px = fx * s + 0.5f, py = fy * s + 0.5f;
                float fpx = floorf(px), fpy = floorf(py);
                float wx = px - fpx, wy = py - fpy;
                uint32_t ux = (uint32_t)fpx, uy = (uint32_t)fpy;
                uint32_t x0 = min(ux, R - 1u), x1 = min(ux + 1u, R - 1u);
                uint32_t y0 = min(uy, R - 1u), y1 = min(uy + 1u, R - 1u);
                uint32_t i00, i10, i01, i11;
                if (l < 11) {   // dense levels
                    i00 = x0 + y0 * R; i10 = x1 + y0 * R;
                    i01 = x0 + y1 * R; i11 = x1 + y1 * R;
                } else {        // hashed level
                    uint32_t h0 = y0 * 2654435761u, h1 = y1 * 2654435761u;
                    i00 = (x0 ^ h0) & (TBL - 1u); i10 = (x1 ^ h0) & (TBL - 1u);
                    i01 = (x0 ^ h1) & (TBL - 1u); i11 = (x1 ^ h1) & (TBL - 1u);
                }
                const float4* base = tab + ((size_t)l << 20);
                float4 t00 = __ldg(base + i00), t10 = __ldg(base + i10);
                float4 t01 = __ldg(base + i01), t11 = __ldg(base + i11);
                float w00 = (1.f - wx) * (1.f - wy), w10 = wx * (1.f - wy);
                float w01 = (1.f - wx) * wy,         w11 = wx * wy;
                float4 o;
                o.x = tf32r(t00.x * w00 + t10.x * w10 + t01.x * w01 + t11.x * w11);
                o.y = tf32r(t00.y * w00 + t10.y * w10 + t01.y * w01 + t11.y * w11);
                o.z = tf32r(t00.z * w00 + t10.z * w10 + t01.z * w01 + t11.z * w11);
                o.w = tf32r(t00.w * w00 + t10.w * w10 + t01.w * w01 + t11.w * w11);
                *(float4*)&Xs[r * XS_STRIDE + l * 4] = o;
            }
        }
        __syncwarp();

        // ---------------- GEMM1: H1 = relu(X @ W1), X 16x48 per warp --------
        float acc[16][4];
#pragma unroll
        for (int n = 0; n < 16; n++) { acc[n][0] = 0.f; acc[n][1] = 0.f; acc[n][2] = 0.f; acc[n][3] = 0.f; }
        {
            float a[6][4];
#pragma unroll
            for (int k = 0; k < 6; k++) {
                const float* p0 = &Xs[(m0 + g) * XS_STRIDE + k * 8 + cq];
                a[k][0] = p0[0];
                a[k][1] = p0[8 * XS_STRIDE];
                a[k][2] = p0[4];
                a[k][3] = p0[8 * XS_STRIDE + 4];
            }
#pragma unroll
            for (int k = 0; k < 6; k++) {
#pragma unroll
                for (int n = 0; n < 16; n++) {
                    float b0 = W1s[(k * 8 + cq) * W_STRIDE + n * 8 + g];
                    float b1 = W1s[(k * 8 + cq + 4) * W_STRIDE + n * 8 + g];
                    mma8(acc[n], a[k], b0, b1);
                }
            }
        }
        // relu + tf32-round, store H1 (warp-local rows)
#pragma unroll
        for (int n = 0; n < 16; n++) {
            float2 v0, v1;
            v0.x = tf32r(fmaxf(acc[n][0], 0.f)); v0.y = tf32r(fmaxf(acc[n][1], 0.f));
            v1.x = tf32r(fmaxf(acc[n][2], 0.f)); v1.y = tf32r(fmaxf(acc[n][3], 0.f));
            *(float2*)&H1s[(m0 + g) * H1_STRIDE + n * 8 + 2 * cq] = v0;
            *(float2*)&H1s[(m0 + g + 8) * H1_STRIDE + n * 8 + 2 * cq] = v1;
        }
        __syncwarp();

        // ---------------- GEMM2: H2 = H1 @ W2 (relu fused into epilogue) ----
        float a2[16][4];
#pragma unroll
        for (int k = 0; k < 16; k++) {
            const float* p0 = &H1s[(m0 + g) * H1_STRIDE + k * 8 + cq];
            a2[k][0] = p0[0];
            a2[k][1] = p0[8 * H1_STRIDE];
            a2[k][2] = p0[4];
            a2[k][3] = p0[8 * H1_STRIDE + 4];
        }
#pragma unroll
        for (int n = 0; n < 16; n++) { acc[n][0] = 0.f; acc[n][1] = 0.f; acc[n][2] = 0.f; acc[n][3] = 0.f; }
#pragma unroll
        for (int k = 0; k < 16; k++) {
#pragma unroll
            for (int n = 0; n < 16; n++) {
                float b0 = W2s[(k * 8 + cq) * W_STRIDE + n * 8 + g];
                float b1 = W2s[(k * 8 + cq + 4) * W_STRIDE + n * 8 + g];
                mma8(acc[n], a2[k], b0, b1);
            }
        }

        // ---------------- epilogue: out = relu(H2) . w3 ---------------------
        float s0 = 0.f, s1 = 0.f;
#pragma unroll
        for (int n = 0; n < 16; n++) {
            float wa = w3s[n * 8 + 2 * cq], wb = w3s[n * 8 + 2 * cq + 1];
            s0 += fmaxf(acc[n][0], 0.f) * wa + fmaxf(acc[n][1], 0.f) * wb;
            s1 += fmaxf(acc[n][2], 0.f) * wa + fmaxf(acc[n][3], 0.f) * wb;
        }
        s0 += __shfl_xor_sync(0xffffffffu, s0, 1);
        s0 += __shfl_xor_sync(0xffffffffu, s0, 2);
        s1 += __shfl_xor_sync(0xffffffffu, s1, 1);
        s1 += __shfl_xor_sync(0xffffffffu, s1, 2);
        if (cq == 0) {
            int r0 = m0 + g;
            out[((ty << 3) + (r0 >> 4)) * IMG + (tx << 4) + (r0 & 15)] = s0;
            int r1 = r0 + 8;
            out[((ty << 3) + (r1 >> 4)) * IMG + (tx << 4) + (r1 & 15)] = s1;
        }
        __syncwarp();
    }
}

extern "C" void kernel_launch(void* const* d_in, const int* in_sizes, int n_in,
                              void* d_out, int out_size) {
    // robust input detection by element counts (H/W scalars are unused: fixed 1024)
    const float* table = nullptr;
    const float* w1 = nullptr;
    const float* w2 = nullptr;
    const float* w3 = nullptr;
    for (int i = 0; i < n_in; i++) {
        switch (in_sizes[i]) {
            case 12 * 1048576 * 4: table = (const float*)d_in[i]; break;
            case 48 * 128:         w1 = (const float*)d_in[i]; break;
            case 128 * 128:        w2 = (const float*)d_in[i]; break;
            case 128:              w3 = (const float*)d_in[i]; break;
            default: break;
        }
    }
    if (!table) table = (const float*)d_in[2];
    if (!w1) w1 = (const float*)d_in[3];
    if (!w2) w2 = (const float*)d_in[4];
    if (!w3) w3 = (const float*)d_in[5];

    cudaFuncSetAttribute(inr_kernel, cudaFuncAttributeMaxDynamicSharedMemorySize, SMEM_BYTES);
    inr_kernel<<<NCTA, 256, SMEM_BYTES>>>((const float4*)table, w1, w2, w3, (float*)d_out);
}

// round 5
// speedup vs baseline: 1.7266x; 1.7266x over previous
#include <cuda_runtime.h>
#include <cuda_fp16.h>
#include <stdint.h>

// ---------------------------------------------------------------------------
// TCNN INR fused: hash-grid encoding + MLP 48->128->128->1, fp16 HMMA path.
// 8 warps = 2 M-groups (64 rows) x 4 N-groups (32 cols); weight (B) fragments
// held persistently in registers -> zero B smem traffic in the main loop.
// Encodings scaled by 2^14 to dodge fp16 subnormals (undone in epilogue).
// ---------------------------------------------------------------------------

#define IMG 1024
#define NBATCH 8192            // 1024*1024 / 128 pixels per tile
#define TILES_PER_CTA 8
#define NCTA 1024
#define SCALE 16384.0f
#define INV_SCALE (1.0f / 16384.0f)

// smem layout (halves / floats)
#define XS_STRIDE_H 56         // 48 cols + pad  (112B rows)
#define H1_STRIDE_H 136        // 128 cols + pad (272B rows)
#define SM_X_BYTES (128 * XS_STRIDE_H * 2)            // 14336
#define SM_H1_BYTES (128 * H1_STRIDE_H * 2)           // 34816
#define SM_PART_BYTES (4 * 128 * 4)                   // 2048
#define SMEM_BYTES (SM_X_BYTES + SM_H1_BYTES + SM_PART_BYTES)

__constant__ float c_scale[12] = {
    15.0f, 23.0f, 35.0f, 53.0f, 80.0f, 120.5f, 181.25f, 272.375f,
    409.0625f, 614.09375f, 921.640625f, 1382.9609375f};
__constant__ uint32_t c_res[12] = {16, 24, 36, 54, 81, 122, 183, 274, 411, 616, 923, 1384};

static __device__ __forceinline__ uint32_t packh2(float lo, float hi) {
    __half2 h = __floats2half2_rn(lo, hi);
    return *(uint32_t*)&h;
}

// D += A(16x16 f16) * B(16x8 f16), f32 accum
static __device__ __forceinline__ void mma16(float d[4], const uint32_t a[4], const uint32_t b[2]) {
    asm volatile(
        "mma.sync.aligned.m16n8k16.row.col.f32.f16.f16.f32 "
        "{%0,%1,%2,%3}, {%4,%5,%6,%7}, {%8,%9}, {%0,%1,%2,%3};"
        : "+f"(d[0]), "+f"(d[1]), "+f"(d[2]), "+f"(d[3])
        : "r"(a[0]), "r"(a[1]), "r"(a[2]), "r"(a[3]), "r"(b[0]), "r"(b[1]));
}

__global__ __launch_bounds__(256, 1) void inr_kernel(
    const float4* __restrict__ tab,   // [12][2^20] float4
    const float* __restrict__ w1,     // [48][128]
    const float* __restrict__ w2,     // [128][128]
    const float* __restrict__ w3,     // [128]
    float* __restrict__ out)          // [1024*1024]
{
    extern __shared__ char smem[];
    __half* Xh = (__half*)smem;                       // [128][56]
    __half* H1h = (__half*)(smem + SM_X_BYTES);       // [128][136]
    float* part = (float*)(smem + SM_X_BYTES + SM_H1_BYTES);  // [4][128]
    uint32_t* Xw = (uint32_t*)Xh;
    uint32_t* H1w = (uint32_t*)H1h;

    const int tid = threadIdx.x;
    const int lane = tid & 31, wid = tid >> 5;
    const int q = lane & 3, ln4 = lane >> 2;
    const int mg = wid >> 2;           // M-group: rows mg*64 .. +63
    const int ng = wid & 3;            // N-group: cols ng*32 .. +31

    // ---- persistent B fragments (weights), loaded once from global ----
    uint32_t B1[3][4][2];   // GEMM1: K=48 (3 k-steps), 4 n-tiles
    uint32_t B2[8][4][2];   // GEMM2: K=128 (8 k-steps)
    float w3a[4], w3b[4];
#pragma unroll
    for (int s = 0; s < 3; s++)
#pragma unroll
        for (int nt = 0; nt < 4; nt++) {
            int kb = s * 16 + 2 * q;
            int n = ng * 32 + nt * 8 + ln4;
            B1[s][nt][0] = packh2(w1[(kb + 0) * 128 + n], w1[(kb + 1) * 128 + n]);
            B1[s][nt][1] = packh2(w1[(kb + 8) * 128 + n], w1[(kb + 9) * 128 + n]);
        }
#pragma unroll
    for (int s = 0; s < 8; s++)
#pragma unroll
        for (int nt = 0; nt < 4; nt++) {
            int kb = s * 16 + 2 * q;
            int n = ng * 32 + nt * 8 + ln4;
            B2[s][nt][0] = packh2(w2[(kb + 0) * 128 + n], w2[(kb + 1) * 128 + n]);
            B2[s][nt][1] = packh2(w2[(kb + 8) * 128 + n], w2[(kb + 9) * 128 + n]);
        }
#pragma unroll
    for (int nt = 0; nt < 4; nt++) {
        w3a[nt] = w3[ng * 32 + nt * 8 + 2 * q];
        w3b[nt] = w3[ng * 32 + nt * 8 + 2 * q + 1];
    }

    for (int it = 0; it < TILES_PER_CTA; ++it) {
        const int b = blockIdx.x * TILES_PER_CTA + it;

        // ---------------- encoding: 2 threads / pixel, 6 levels each --------
        {
            const int r = tid >> 1;                 // pixel row in batch
            const int pix = b * 128 + r;
            const float fx = (float)(pix & 1023) * (1.0f / 1023.0f);
            const float fy = (float)(pix >> 10) * (1.0f / 1023.0f);
            const int l0 = (tid & 1) * 6;
            uint2* dst = (uint2*)(Xh + r * XS_STRIDE_H);
#pragma unroll
            for (int j = 0; j < 6; j++) {
                const int l = l0 + j;
                const float s = c_scale[l];
                const uint32_t R = c_res[l];
                float px = fx * s + 0.5f, py = fy * s + 0.5f;
                float fpx = floorf(px), fpy = floorf(py);
                float wx = px - fpx, wy = py - fpy;
                uint32_t ux = (uint32_t)fpx, uy = (uint32_t)fpy;
                uint32_t x0 = min(ux, R - 1u), x1 = min(ux + 1u, R - 1u);
                uint32_t y0 = min(uy, R - 1u), y1 = min(uy + 1u, R - 1u);
                uint32_t i00, i10, i01, i11;
                if (l < 11) {
                    i00 = x0 + y0 * R; i10 = x1 + y0 * R;
                    i01 = x0 + y1 * R; i11 = x1 + y1 * R;
                } else {
                    uint32_t h0 = y0 * 2654435761u, h1 = y1 * 2654435761u;
                    i00 = (x0 ^ h0) & 0xFFFFFu; i10 = (x1 ^ h0) & 0xFFFFFu;
                    i01 = (x0 ^ h1) & 0xFFFFFu; i11 = (x1 ^ h1) & 0xFFFFFu;
                }
                const float4* base = tab + ((size_t)l << 20);
                float4 t00 = __ldg(base + i00), t10 = __ldg(base + i10);
                float4 t01 = __ldg(base + i01), t11 = __ldg(base + i11);
                float w00 = (1.f - wx) * (1.f - wy) * SCALE, w10 = wx * (1.f - wy) * SCALE;
                float w01 = (1.f - wx) * wy * SCALE,         w11 = wx * wy * SCALE;
                float e0 = t00.x * w00 + t10.x * w10 + t01.x * w01 + t11.x * w11;
                float e1 = t00.y * w00 + t10.y * w10 + t01.y * w01 + t11.y * w11;
                float e2 = t00.z * w00 + t10.z * w10 + t01.z * w01 + t11.z * w11;
                float e3 = t00.w * w00 + t10.w * w10 + t01.w * w01 + t11.w * w11;
                uint2 v;
                v.x = packh2(e0, e1);
                v.y = packh2(e2, e3);
                dst[l] = v;
            }
        }
        __syncthreads();

        // ---------------- GEMM1: H1 = relu(X @ W1) --------------------------
        float acc[4][4][4];
#pragma unroll
        for (int mt = 0; mt < 4; mt++)
#pragma unroll
            for (int nt = 0; nt < 4; nt++) {
                acc[mt][nt][0] = 0.f; acc[mt][nt][1] = 0.f;
                acc[mt][nt][2] = 0.f; acc[mt][nt][3] = 0.f;
            }
#pragma unroll
        for (int s = 0; s < 3; s++) {
            uint32_t a[4][4];
#pragma unroll
            for (int mt = 0; mt < 4; mt++) {
                int r0 = mg * 64 + mt * 16 + ln4;
                int cw = s * 8 + q;
                a[mt][0] = Xw[r0 * (XS_STRIDE_H / 2) + cw];
                a[mt][1] = Xw[(r0 + 8) * (XS_STRIDE_H / 2) + cw];
                a[mt][2] = Xw[r0 * (XS_STRIDE_H / 2) + cw + 4];
                a[mt][3] = Xw[(r0 + 8) * (XS_STRIDE_H / 2) + cw + 4];
            }
#pragma unroll
            for (int mt = 0; mt < 4; mt++)
#pragma unroll
                for (int nt = 0; nt < 4; nt++)
                    mma16(acc[mt][nt], a[mt], B1[s][nt]);
        }
        // relu -> fp16 -> H1 smem
#pragma unroll
        for (int mt = 0; mt < 4; mt++) {
            int r0 = mg * 64 + mt * 16 + ln4;
#pragma unroll
            for (int nt = 0; nt < 4; nt++) {
                int cw = ng * 16 + nt * 4 + q;
                H1w[r0 * (H1_STRIDE_H / 2) + cw] =
                    packh2(fmaxf(acc[mt][nt][0], 0.f), fmaxf(acc[mt][nt][1], 0.f));
                H1w[(r0 + 8) * (H1_STRIDE_H / 2) + cw] =
                    packh2(fmaxf(acc[mt][nt][2], 0.f), fmaxf(acc[mt][nt][3], 0.f));
            }
        }
        __syncthreads();

        // ---------------- GEMM2: H2 = H1 @ W2 -------------------------------
#pragma unroll
        for (int mt = 0; mt < 4; mt++)
#pragma unroll
            for (int nt = 0; nt < 4; nt++) {
                acc[mt][nt][0] = 0.f; acc[mt][nt][1] = 0.f;
                acc[mt][nt][2] = 0.f; acc[mt][nt][3] = 0.f;
            }
#pragma unroll
        for (int s = 0; s < 8; s++) {
            uint32_t a[4][4];
#pragma unroll
            for (int mt = 0; mt < 4; mt++) {
                int r0 = mg * 64 + mt * 16 + ln4;
                int cw = s * 8 + q;
                a[mt][0] = H1w[r0 * (H1_STRIDE_H / 2) + cw];
                a[mt][1] = H1w[(r0 + 8) * (H1_STRIDE_H / 2) + cw];
                a[mt][2] = H1w[r0 * (H1_STRIDE_H / 2) + cw + 4];
                a[mt][3] = H1w[(r0 + 8) * (H1_STRIDE_H / 2) + cw + 4];
            }
#pragma unroll
            for (int mt = 0; mt < 4; mt++)
#pragma unroll
                for (int nt = 0; nt < 4; nt++)
                    mma16(acc[mt][nt], a[mt], B2[s][nt]);
        }

        // ---------------- epilogue: partial relu(H2).w3 per N-group ---------
#pragma unroll
        for (int mt = 0; mt < 4; mt++) {
            float s0 = 0.f, s1 = 0.f;
#pragma unroll
            for (int nt = 0; nt < 4; nt++) {
                s0 += fmaxf(acc[mt][nt][0], 0.f) * w3a[nt] + fmaxf(acc[mt][nt][1], 0.f) * w3b[nt];
                s1 += fmaxf(acc[mt][nt][2], 0.f) * w3a[nt] + fmaxf(acc[mt][nt][3], 0.f) * w3b[nt];
            }
            s0 += __shfl_xor_sync(0xffffffffu, s0, 1);
            s0 += __shfl_xor_sync(0xffffffffu, s0, 2);
            s1 += __shfl_xor_sync(0xffffffffu, s1, 1);
            s1 += __shfl_xor_sync(0xffffffffu, s1, 2);
            if (q == 0) {
                int r0 = mg * 64 + mt * 16 + ln4;
                part[ng * 128 + r0] = s0;
                part[ng * 128 + r0 + 8] = s1;
            }
        }
        __syncthreads();

        if (tid < 128) {
            float o = (part[tid] + part[128 + tid] + part[256 + tid] + part[384 + tid]) * INV_SCALE;
            out[b * 128 + tid] = o;
        }
        __syncthreads();
    }
}

extern "C" void kernel_launch(void* const* d_in, const int* in_sizes, int n_in,
                              void* d_out, int out_size) {
    const float* table = nullptr;
    const float* w1 = nullptr;
    const float* w2 = nullptr;
    const float* w3 = nullptr;
    for (int i = 0; i < n_in; i++) {
        switch (in_sizes[i]) {
            case 12 * 1048576 * 4: table = (const float*)d_in[i]; break;
            case 48 * 128:         w1 = (const float*)d_in[i]; break;
            case 128 * 128:        w2 = (const float*)d_in[i]; break;
            case 128:              w3 = (const float*)d_in[i]; break;
            default: break;
        }
    }
    if (!table) table = (const float*)d_in[2];
    if (!w1) w1 = (const float*)d_in[3];
    if (!w2) w2 = (const float*)d_in[4];
    if (!w3) w3 = (const float*)d_in[5];

    cudaFuncSetAttribute(inr_kernel, cudaFuncAttributeMaxDynamicSharedMemorySize, SMEM_BYTES);
    inr_kernel<<<NCTA, 256, SMEM_BYTES>>>((const float4*)table, w1, w2, w3, (float*)d_out);
}

// round 6
// speedup vs baseline: 2.1333x; 1.2356x over previous
#include <cuda_runtime.h>
#include <cuda_fp16.h>
#include <stdint.h>

// ---------------------------------------------------------------------------
// TCNN INR fused: hash-grid encoding + MLP 48->128->128->1, fp16 HMMA path.
// 128-thread CTAs (M=64 pixels, 4 warps = 4 N-groups of 32 cols), 2 CTAs/SM
// for cross-CTA phase overlap (encode LSU phase vs GEMM tensor phase).
// Weights persistent in registers; A-frags via ldmatrix, H1 via stmatrix.
// Encodings scaled by 2^14 to dodge fp16 subnormals (undone in epilogue).
// ---------------------------------------------------------------------------

#define IMG 1024
#define TILES_PER_CTA 8
#define NCTA 2048              // 2048 * 8 batches of 64 pixels = 1024*1024
#define SCALE 16384.0f
#define INV_SCALE (1.0f / 16384.0f)

#define XS_STRIDE_H 56         // 48 cols + pad (112B rows, 16B-aligned)
#define H1_STRIDE_H 136        // 128 cols + pad (272B rows, 16B-aligned)
#define SM_X_BYTES (64 * XS_STRIDE_H * 2)     // 7168
#define SM_H1_BYTES (64 * H1_STRIDE_H * 2)    // 17408
#define SM_PART_BYTES (4 * 64 * 4)            // 1024
#define SMEM_BYTES (SM_X_BYTES + SM_H1_BYTES + SM_PART_BYTES)

__constant__ float c_scale[12] = {
    15.0f, 23.0f, 35.0f, 53.0f, 80.0f, 120.5f, 181.25f, 272.375f,
    409.0625f, 614.09375f, 921.640625f, 1382.9609375f};
__constant__ uint32_t c_res[12] = {16, 24, 36, 54, 81, 122, 183, 274, 411, 616, 923, 1384};

static __device__ __forceinline__ uint32_t packh2(float lo, float hi) {
    __half2 h = __floats2half2_rn(lo, hi);
    return *(uint32_t*)&h;
}

static __device__ __forceinline__ void mma16(float d[4], const uint32_t a[4], const uint32_t b[2]) {
    asm volatile(
        "mma.sync.aligned.m16n8k16.row.col.f32.f16.f16.f32 "
        "{%0,%1,%2,%3}, {%4,%5,%6,%7}, {%8,%9}, {%0,%1,%2,%3};"
        : "+f"(d[0]), "+f"(d[1]), "+f"(d[2]), "+f"(d[3])
        : "r"(a[0]), "r"(a[1]), "r"(a[2]), "r"(a[3]), "r"(b[0]), "r"(b[1]));
}

#define LDSM_X4(r, addr) \
    asm volatile("ldmatrix.sync.aligned.m8n8.x4.shared.b16 {%0,%1,%2,%3}, [%4];" \
        : "=r"((r)[0]), "=r"((r)[1]), "=r"((r)[2]), "=r"((r)[3]) : "r"(addr))

#define STSM_X4(addr, r0, r1, r2, r3) \
    asm volatile("stmatrix.sync.aligned.m8n8.x4.shared.b16 [%0], {%1,%2,%3,%4};" \
        :: "r"(addr), "r"(r0), "r"(r1), "r"(r2), "r"(r3) : "memory")

__global__ __launch_bounds__(128, 2) void inr_kernel(
    const float4* __restrict__ tab,   // [12][2^20] float4
    const float* __restrict__ w1,     // [48][128]
    const float* __restrict__ w2,     // [128][128]
    const float* __restrict__ w3,     // [128]
    float* __restrict__ out)          // [1024*1024]
{
    extern __shared__ char smem[];
    __half* Xh = (__half*)smem;                       // [64][56]
    __half* H1h = (__half*)(smem + SM_X_BYTES);       // [64][136]
    float* part = (float*)(smem + SM_X_BYTES + SM_H1_BYTES);  // [4][64]

    const uint32_t Xu = (uint32_t)__cvta_generic_to_shared(Xh);
    const uint32_t H1u = (uint32_t)__cvta_generic_to_shared(H1h);

    const int tid = threadIdx.x;
    const int lane = tid & 31, ng = tid >> 5;   // warp = N-group (32 cols)
    const int q = lane & 3, ln4 = lane >> 2;

    // ldmatrix/stmatrix lane address components: row = lane&15, col-half sel = lane>>4
    const int lrow = lane & 15;
    const int lcol = (lane >> 4) << 3;          // 0 or 8 halves

    // ---- persistent B fragments (weights), loaded once from global ----
    uint32_t B1[3][4][2];
    uint32_t B2[8][4][2];
    float w3a[4], w3b[4];
#pragma unroll
    for (int s = 0; s < 3; s++)
#pragma unroll
        for (int nt = 0; nt < 4; nt++) {
            int kb = s * 16 + 2 * q;
            int n = ng * 32 + nt * 8 + ln4;
            B1[s][nt][0] = packh2(w1[(kb + 0) * 128 + n], w1[(kb + 1) * 128 + n]);
            B1[s][nt][1] = packh2(w1[(kb + 8) * 128 + n], w1[(kb + 9) * 128 + n]);
        }
#pragma unroll
    for (int s = 0; s < 8; s++)
#pragma unroll
        for (int nt = 0; nt < 4; nt++) {
            int kb = s * 16 + 2 * q;
            int n = ng * 32 + nt * 8 + ln4;
            B2[s][nt][0] = packh2(w2[(kb + 0) * 128 + n], w2[(kb + 1) * 128 + n]);
            B2[s][nt][1] = packh2(w2[(kb + 8) * 128 + n], w2[(kb + 9) * 128 + n]);
        }
#pragma unroll
    for (int nt = 0; nt < 4; nt++) {
        w3a[nt] = w3[ng * 32 + nt * 8 + 2 * q];
        w3b[nt] = w3[ng * 32 + nt * 8 + 2 * q + 1];
    }

    // per-lane smem base addresses for matrix ops (bytes)
    const uint32_t xlda = Xu + (uint32_t)(lrow * XS_STRIDE_H + lcol) * 2;
    const uint32_t h1lda = H1u + (uint32_t)(lrow * H1_STRIDE_H + lcol) * 2;
    const uint32_t h1sta = H1u + (uint32_t)(lrow * H1_STRIDE_H + ng * 32 + lcol) * 2;

    for (int it = 0; it < TILES_PER_CTA; ++it) {
        const int b = blockIdx.x * TILES_PER_CTA + it;

        // ---------------- encoding: 2 threads / pixel, 6 levels each --------
        {
            const int r = tid >> 1;                 // pixel row 0..63
            const int pix = b * 64 + r;
            const float fx = (float)(pix & 1023) * (1.0f / 1023.0f);
            const float fy = (float)(pix >> 10) * (1.0f / 1023.0f);
            const int l0 = (tid & 1) * 6;
            uint2* dst = (uint2*)(Xh + r * XS_STRIDE_H);
#pragma unroll
            for (int j = 0; j < 6; j++) {
                const int l = l0 + j;
                const float s = c_scale[l];
                const uint32_t R = c_res[l];
                float px = fx * s + 0.5f, py = fy * s + 0.5f;
                float fpx = floorf(px), fpy = floorf(py);
                float wx = px - fpx, wy = py - fpy;
                uint32_t ux = (uint32_t)fpx, uy = (uint32_t)fpy;
                uint32_t x0 = min(ux, R - 1u), x1 = min(ux + 1u, R - 1u);
                uint32_t y0 = min(uy, R - 1u), y1 = min(uy + 1u, R - 1u);
                uint32_t i00, i10, i01, i11;
                if (l < 11) {
                    i00 = x0 + y0 * R; i10 = x1 + y0 * R;
                    i01 = x0 + y1 * R; i11 = x1 + y1 * R;
                } else {
                    uint32_t h0 = y0 * 2654435761u, h1 = y1 * 2654435761u;
                    i00 = (x0 ^ h0) & 0xFFFFFu; i10 = (x1 ^ h0) & 0xFFFFFu;
                    i01 = (x0 ^ h1) & 0xFFFFFu; i11 = (x1 ^ h1) & 0xFFFFFu;
                }
                const float4* base = tab + ((size_t)l << 20);
                float4 t00 = __ldg(base + i00), t10 = __ldg(base + i10);
                float4 t01 = __ldg(base + i01), t11 = __ldg(base + i11);
                float w00 = (1.f - wx) * (1.f - wy) * SCALE, w10 = wx * (1.f - wy) * SCALE;
                float w01 = (1.f - wx) * wy * SCALE,         w11 = wx * wy * SCALE;
                float e0 = t00.x * w00 + t10.x * w10 + t01.x * w01 + t11.x * w11;
                float e1 = t00.y * w00 + t10.y * w10 + t01.y * w01 + t11.y * w11;
                float e2 = t00.z * w00 + t10.z * w10 + t01.z * w01 + t11.z * w11;
                float e3 = t00.w * w00 + t10.w * w10 + t01.w * w01 + t11.w * w11;
                uint2 v;
                v.x = packh2(e0, e1);
                v.y = packh2(e2, e3);
                dst[l] = v;
            }
        }
        __syncthreads();

        // ---------------- GEMM1: H1 = relu(X @ W1), M=64 --------------------
        float acc[4][4][4];
#pragma unroll
        for (int mt = 0; mt < 4; mt++)
#pragma unroll
            for (int nt = 0; nt < 4; nt++) {
                acc[mt][nt][0] = 0.f; acc[mt][nt][1] = 0.f;
                acc[mt][nt][2] = 0.f; acc[mt][nt][3] = 0.f;
            }
#pragma unroll
        for (int s = 0; s < 3; s++) {
            uint32_t a[4][4];
#pragma unroll
            for (int mt = 0; mt < 4; mt++)
                LDSM_X4(a[mt], xlda + (uint32_t)(mt * 16 * XS_STRIDE_H * 2 + s * 32));
#pragma unroll
            for (int mt = 0; mt < 4; mt++)
#pragma unroll
                for (int nt = 0; nt < 4; nt++)
                    mma16(acc[mt][nt], a[mt], B1[s][nt]);
        }
        // relu -> fp16 -> H1 smem via stmatrix
#pragma unroll
        for (int mt = 0; mt < 4; mt++) {
            uint32_t v[4][2];
#pragma unroll
            for (int nt = 0; nt < 4; nt++) {
                v[nt][0] = packh2(fmaxf(acc[mt][nt][0], 0.f), fmaxf(acc[mt][nt][1], 0.f));
                v[nt][1] = packh2(fmaxf(acc[mt][nt][2], 0.f), fmaxf(acc[mt][nt][3], 0.f));
            }
            uint32_t sa = h1sta + (uint32_t)(mt * 16 * H1_STRIDE_H * 2);
            STSM_X4(sa, v[0][0], v[0][1], v[1][0], v[1][1]);
            STSM_X4(sa + 32, v[2][0], v[2][1], v[3][0], v[3][1]);
        }
        __syncthreads();

        // ---------------- GEMM2: H2 = H1 @ W2 -------------------------------
#pragma unroll
        for (int mt = 0; mt < 4; mt++)
#pragma unroll
            for (int nt = 0; nt < 4; nt++) {
                acc[mt][nt][0] = 0.f; acc[mt][nt][1] = 0.f;
                acc[mt][nt][2] = 0.f; acc[mt][nt][3] = 0.f;
            }
#pragma unroll
        for (int s = 0; s < 8; s++) {
            uint32_t a[4][4];
#pragma unroll
            for (int mt = 0; mt < 4; mt++)
                LDSM_X4(a[mt], h1lda + (uint32_t)(mt * 16 * H1_STRIDE_H * 2 + s * 32));
#pragma unroll
            for (int mt = 0; mt < 4; mt++)
#pragma unroll
                for (int nt = 0; nt < 4; nt++)
                    mma16(acc[mt][nt], a[mt], B2[s][nt]);
        }

        // ---------------- epilogue: partial relu(H2).w3 per N-group ---------
#pragma unroll
        for (int mt = 0; mt < 4; mt++) {
            float s0 = 0.f, s1 = 0.f;
#pragma unroll
            for (int nt = 0; nt < 4; nt++) {
                s0 += fmaxf(acc[mt][nt][0], 0.f) * w3a[nt] + fmaxf(acc[mt][nt][1], 0.f) * w3b[nt];
                s1 += fmaxf(acc[mt][nt][2], 0.f) * w3a[nt] + fmaxf(acc[mt][nt][3], 0.f) * w3b[nt];
            }
            s0 += __shfl_xor_sync(0xffffffffu, s0, 1);
            s0 += __shfl_xor_sync(0xffffffffu, s0, 2);
            s1 += __shfl_xor_sync(0xffffffffu, s1, 1);
            s1 += __shfl_xor_sync(0xffffffffu, s1, 2);
            if (q == 0) {
                int r0 = mt * 16 + ln4;
                part[ng * 64 + r0] = s0;
                part[ng * 64 + r0 + 8] = s1;
            }
        }
        __syncthreads();

        if (tid < 64) {
            float o = (part[tid] + part[64 + tid] + part[128 + tid] + part[192 + tid]) * INV_SCALE;
            out[b * 64 + tid] = o;
        }
        // no trailing barrier needed: next encode's Xh writes are ordered by
        // the post-encode sync, and all Xh readers finished before the H1 sync.
    }
}

extern "C" void kernel_launch(void* const* d_in, const int* in_sizes, int n_in,
                              void* d_out, int out_size) {
    const float* table = nullptr;
    const float* w1 = nullptr;
    const float* w2 = nullptr;
    const float* w3 = nullptr;
    for (int i = 0; i < n_in; i++) {
        switch (in_sizes[i]) {
            case 12 * 1048576 * 4: table = (const float*)d_in[i]; break;
            case 48 * 128:         w1 = (const float*)d_in[i]; break;
            case 128 * 128:        w2 = (const float*)d_in[i]; break;
            case 128:              w3 = (const float*)d_in[i]; break;
            default: break;
        }
    }
    if (!table) table = (const float*)d_in[2];
    if (!w1) w1 = (const float*)d_in[3];
    if (!w2) w2 = (const float*)d_in[4];
    if (!w3) w3 = (const float*)d_in[5];

    cudaFuncSetAttribute(inr_kernel, cudaFuncAttributeMaxDynamicSharedMemorySize, SMEM_BYTES);
    inr_kernel<<<NCTA, 128, SMEM_BYTES>>>((const float4*)table, w1, w2, w3, (float*)d_out);
}

// round 7
// speedup vs baseline: 2.2086x; 1.0353x over previous
#include <cuda_runtime.h>
#include <cuda_fp16.h>
#include <stdint.h>

// ---------------------------------------------------------------------------
// TCNN INR fused: hash-grid encoding + MLP 48->128->128->1, fp16 HMMA path.
// 128-thread CTAs (M=64 pixels, 4 warps = 4 N-groups of 32 cols), 3 CTAs/SM
// (launch_bounds-capped regs) for cross-CTA phase overlap + latency hiding.
// Weights persistent in registers; A-frags via ldmatrix, H1 via stmatrix.
// Encode restructured for high MLP: batch 12 gathers before interpolating.
// Encodings scaled by 2^14 to dodge fp16 subnormals (undone in epilogue).
// ---------------------------------------------------------------------------

#define IMG 1024
#define TILES_PER_CTA 8
#define NCTA 2048              // 2048 * 8 batches of 64 pixels = 1024*1024
#define SCALE 16384.0f
#define INV_SCALE (1.0f / 16384.0f)

#define XS_STRIDE_H 56         // 48 cols + pad (112B rows, 16B-aligned)
#define H1_STRIDE_H 136        // 128 cols + pad (272B rows, 16B-aligned)
#define SM_X_BYTES (64 * XS_STRIDE_H * 2)     // 7168
#define SM_H1_BYTES (64 * H1_STRIDE_H * 2)    // 17408
#define SM_PART_BYTES (4 * 64 * 4)            // 1024
#define SMEM_BYTES (SM_X_BYTES + SM_H1_BYTES + SM_PART_BYTES)

__constant__ float c_scale[12] = {
    15.0f, 23.0f, 35.0f, 53.0f, 80.0f, 120.5f, 181.25f, 272.375f,
    409.0625f, 614.09375f, 921.640625f, 1382.9609375f};
__constant__ uint32_t c_res[12] = {16, 24, 36, 54, 81, 122, 183, 274, 411, 616, 923, 1384};

static __device__ __forceinline__ uint32_t packh2(float lo, float hi) {
    __half2 h = __floats2half2_rn(lo, hi);
    return *(uint32_t*)&h;
}

static __device__ __forceinline__ void mma16(float d[4], const uint32_t a[4], const uint32_t b[2]) {
    asm volatile(
        "mma.sync.aligned.m16n8k16.row.col.f32.f16.f16.f32 "
        "{%0,%1,%2,%3}, {%4,%5,%6,%7}, {%8,%9}, {%0,%1,%2,%3};"
        : "+f"(d[0]), "+f"(d[1]), "+f"(d[2]), "+f"(d[3])
        : "r"(a[0]), "r"(a[1]), "r"(a[2]), "r"(a[3]), "r"(b[0]), "r"(b[1]));
}

#define LDSM_X4(r, addr) \
    asm volatile("ldmatrix.sync.aligned.m8n8.x4.shared.b16 {%0,%1,%2,%3}, [%4];" \
        : "=r"((r)[0]), "=r"((r)[1]), "=r"((r)[2]), "=r"((r)[3]) : "r"(addr))

#define STSM_X4(addr, r0, r1, r2, r3) \
    asm volatile("stmatrix.sync.aligned.m8n8.x4.shared.b16 [%0], {%1,%2,%3,%4};" \
        :: "r"(addr), "r"(r0), "r"(r1), "r"(r2), "r"(r3) : "memory")

__global__ __launch_bounds__(128, 3) void inr_kernel(
    const float4* __restrict__ tab,   // [12][2^20] float4
    const float* __restrict__ w1,     // [48][128]
    const float* __restrict__ w2,     // [128][128]
    const float* __restrict__ w3,     // [128]
    float* __restrict__ out)          // [1024*1024]
{
    extern __shared__ char smem[];
    __half* Xh = (__half*)smem;                       // [64][56]
    __half* H1h = (__half*)(smem + SM_X_BYTES);       // [64][136]
    float* part = (float*)(smem + SM_X_BYTES + SM_H1_BYTES);  // [4][64]

    const uint32_t Xu = (uint32_t)__cvta_generic_to_shared(Xh);
    const uint32_t H1u = (uint32_t)__cvta_generic_to_shared(H1h);

    const int tid = threadIdx.x;
    const int lane = tid & 31, ng = tid >> 5;   // warp = N-group (32 cols)
    const int q = lane & 3, ln4 = lane >> 2;

    const int lrow = lane & 15;
    const int lcol = (lane >> 4) << 3;          // 0 or 8 halves

    // ---- persistent B fragments (weights), loaded once from global ----
    uint32_t B1[3][4][2];
    uint32_t B2[8][4][2];
#pragma unroll
    for (int s = 0; s < 3; s++)
#pragma unroll
        for (int nt = 0; nt < 4; nt++) {
            int kb = s * 16 + 2 * q;
            int n = ng * 32 + nt * 8 + ln4;
            B1[s][nt][0] = packh2(w1[(kb + 0) * 128 + n], w1[(kb + 1) * 128 + n]);
            B1[s][nt][1] = packh2(w1[(kb + 8) * 128 + n], w1[(kb + 9) * 128 + n]);
        }
#pragma unroll
    for (int s = 0; s < 8; s++)
#pragma unroll
        for (int nt = 0; nt < 4; nt++) {
            int kb = s * 16 + 2 * q;
            int n = ng * 32 + nt * 8 + ln4;
            B2[s][nt][0] = packh2(w2[(kb + 0) * 128 + n], w2[(kb + 1) * 128 + n]);
            B2[s][nt][1] = packh2(w2[(kb + 8) * 128 + n], w2[(kb + 9) * 128 + n]);
        }

    // per-lane smem base addresses for matrix ops (bytes)
    const uint32_t xlda = Xu + (uint32_t)(lrow * XS_STRIDE_H + lcol) * 2;
    const uint32_t h1lda = H1u + (uint32_t)(lrow * H1_STRIDE_H + lcol) * 2;
    const uint32_t h1sta = H1u + (uint32_t)(lrow * H1_STRIDE_H + ng * 32 + lcol) * 2;

    for (int it = 0; it < TILES_PER_CTA; ++it) {
        const int b = blockIdx.x * TILES_PER_CTA + it;

        // ------- encoding: 2 threads / pixel, 6 levels each, MLP-batched ----
        {
            const int r = tid >> 1;                 // pixel row 0..63
            const int pix = b * 64 + r;
            const float fx = (float)(pix & 1023) * (1.0f / 1023.0f);
            const float fy = (float)(pix >> 10) * (1.0f / 1023.0f);
            const int l0 = (tid & 1) * 6;
            uint2* dst = (uint2*)(Xh + r * XS_STRIDE_H);
#pragma unroll
            for (int half = 0; half < 2; half++) {
                const int lb = l0 + half * 3;
                float4 t[3][4];
                float wxs[3], wys[3];
                // phase 1: all index math + issue 12 gathers (high MLP)
#pragma unroll
                for (int j = 0; j < 3; j++) {
                    const int l = lb + j;
                    const float s = c_scale[l];
                    const uint32_t R = c_res[l];
                    float px = fx * s + 0.5f, py = fy * s + 0.5f;
                    float fpx = floorf(px), fpy = floorf(py);
                    wxs[j] = px - fpx; wys[j] = py - fpy;
                    uint32_t ux = (uint32_t)fpx, uy = (uint32_t)fpy;
                    uint32_t x0 = min(ux, R - 1u), x1 = min(ux + 1u, R - 1u);
                    uint32_t y0 = min(uy, R - 1u), y1 = min(uy + 1u, R - 1u);
                    uint32_t i00, i10, i01, i11;
                    if (l < 11) {
                        i00 = x0 + y0 * R; i10 = x1 + y0 * R;
                        i01 = x0 + y1 * R; i11 = x1 + y1 * R;
                    } else {
                        uint32_t h0 = y0 * 2654435761u, h1 = y1 * 2654435761u;
                        i00 = (x0 ^ h0) & 0xFFFFFu; i10 = (x1 ^ h0) & 0xFFFFFu;
                        i01 = (x0 ^ h1) & 0xFFFFFu; i11 = (x1 ^ h1) & 0xFFFFFu;
                    }
                    const float4* base = tab + ((size_t)l << 20);
                    t[j][0] = __ldg(base + i00);
                    t[j][1] = __ldg(base + i10);
                    t[j][2] = __ldg(base + i01);
                    t[j][3] = __ldg(base + i11);
                }
                // phase 2: interpolate + store
#pragma unroll
                for (int j = 0; j < 3; j++) {
                    float wx = wxs[j], wy = wys[j];
                    float w00 = (1.f - wx) * (1.f - wy) * SCALE, w10 = wx * (1.f - wy) * SCALE;
                    float w01 = (1.f - wx) * wy * SCALE,         w11 = wx * wy * SCALE;
                    float e0 = t[j][0].x * w00 + t[j][1].x * w10 + t[j][2].x * w01 + t[j][3].x * w11;
                    float e1 = t[j][0].y * w00 + t[j][1].y * w10 + t[j][2].y * w01 + t[j][3].y * w11;
                    float e2 = t[j][0].z * w00 + t[j][1].z * w10 + t[j][2].z * w01 + t[j][3].z * w11;
                    float e3 = t[j][0].w * w00 + t[j][1].w * w10 + t[j][2].w * w01 + t[j][3].w * w11;
                    uint2 v;
                    v.x = packh2(e0, e1);
                    v.y = packh2(e2, e3);
                    dst[lb + j] = v;
                }
            }
        }
        __syncthreads();

        // ---------------- GEMM1: H1 = relu(X @ W1), M=64 --------------------
        float acc[4][4][4];
#pragma unroll
        for (int mt = 0; mt < 4; mt++)
#pragma unroll
            for (int nt = 0; nt < 4; nt++) {
                acc[mt][nt][0] = 0.f; acc[mt][nt][1] = 0.f;
                acc[mt][nt][2] = 0.f; acc[mt][nt][3] = 0.f;
            }
#pragma unroll
        for (int s = 0; s < 3; s++) {
            uint32_t a[4][4];
#pragma unroll
            for (int mt = 0; mt < 4; mt++)
                LDSM_X4(a[mt], xlda + (uint32_t)(mt * 16 * XS_STRIDE_H * 2 + s * 32));
#pragma unroll
            for (int mt = 0; mt < 4; mt++)
#pragma unroll
                for (int nt = 0; nt < 4; nt++)
                    mma16(acc[mt][nt], a[mt], B1[s][nt]);
        }
        // relu -> fp16 -> H1 smem via stmatrix
#pragma unroll
        for (int mt = 0; mt < 4; mt++) {
            uint32_t v[4][2];
#pragma unroll
            for (int nt = 0; nt < 4; nt++) {
                v[nt][0] = packh2(fmaxf(acc[mt][nt][0], 0.f), fmaxf(acc[mt][nt][1], 0.f));
                v[nt][1] = packh2(fmaxf(acc[mt][nt][2], 0.f), fmaxf(acc[mt][nt][3], 0.f));
            }
            uint32_t sa = h1sta + (uint32_t)(mt * 16 * H1_STRIDE_H * 2);
            STSM_X4(sa, v[0][0], v[0][1], v[1][0], v[1][1]);
            STSM_X4(sa + 32, v[2][0], v[2][1], v[3][0], v[3][1]);
        }
        __syncthreads();

        // ---------------- GEMM2: H2 = H1 @ W2 -------------------------------
#pragma unroll
        for (int mt = 0; mt < 4; mt++)
#pragma unroll
            for (int nt = 0; nt < 4; nt++) {
                acc[mt][nt][0] = 0.f; acc[mt][nt][1] = 0.f;
                acc[mt][nt][2] = 0.f; acc[mt][nt][3] = 0.f;
            }
#pragma unroll
        for (int s = 0; s < 8; s++) {
            uint32_t a[4][4];
#pragma unroll
            for (int mt = 0; mt < 4; mt++)
                LDSM_X4(a[mt], h1lda + (uint32_t)(mt * 16 * H1_STRIDE_H * 2 + s * 32));
#pragma unroll
            for (int mt = 0; mt < 4; mt++)
#pragma unroll
                for (int nt = 0; nt < 4; nt++)
                    mma16(acc[mt][nt], a[mt], B2[s][nt]);
        }

        // ---------------- epilogue: partial relu(H2).w3 per N-group ---------
        {
            float w3a[4], w3b[4];
#pragma unroll
            for (int nt = 0; nt < 4; nt++) {
                w3a[nt] = __ldg(w3 + ng * 32 + nt * 8 + 2 * q);
                w3b[nt] = __ldg(w3 + ng * 32 + nt * 8 + 2 * q + 1);
            }
#pragma unroll
            for (int mt = 0; mt < 4; mt++) {
                float s0 = 0.f, s1 = 0.f;
#pragma unroll
                for (int nt = 0; nt < 4; nt++) {
                    s0 += fmaxf(acc[mt][nt][0], 0.f) * w3a[nt] + fmaxf(acc[mt][nt][1], 0.f) * w3b[nt];
                    s1 += fmaxf(acc[mt][nt][2], 0.f) * w3a[nt] + fmaxf(acc[mt][nt][3], 0.f) * w3b[nt];
                }
                s0 += __shfl_xor_sync(0xffffffffu, s0, 1);
                s0 += __shfl_xor_sync(0xffffffffu, s0, 2);
                s1 += __shfl_xor_sync(0xffffffffu, s1, 1);
                s1 += __shfl_xor_sync(0xffffffffu, s1, 2);
                if (q == 0) {
                    int r0 = mt * 16 + ln4;
                    part[ng * 64 + r0] = s0;
                    part[ng * 64 + r0 + 8] = s1;
                }
            }
        }
        __syncthreads();

        if (tid < 64) {
            float o = (part[tid] + part[64 + tid] + part[128 + tid] + part[192 + tid]) * INV_SCALE;
            out[b * 64 + tid] = o;
        }
        // next encode's Xh writes are ordered by the post-encode sync;
        // all Xh readers finished before the H1 sync -> no trailing barrier.
    }
}

extern "C" void kernel_launch(void* const* d_in, const int* in_sizes, int n_in,
                              void* d_out, int out_size) {
    const float* table = nullptr;
    const float* w1 = nullptr;
    const float* w2 = nullptr;
    const float* w3 = nullptr;
    for (int i = 0; i < n_in; i++) {
        switch (in_sizes[i]) {
            case 12 * 1048576 * 4: table = (const float*)d_in[i]; break;
            case 48 * 128:         w1 = (const float*)d_in[i]; break;
            case 128 * 128:        w2 = (const float*)d_in[i]; break;
            case 128:              w3 = (const float*)d_in[i]; break;
            default: break;
        }
    }
    if (!table) table = (const float*)d_in[2];
    if (!w1) w1 = (const float*)d_in[3];
    if (!w2) w2 = (const float*)d_in[4];
    if (!w3) w3 = (const float*)d_in[5];

    cudaFuncSetAttribute(inr_kernel, cudaFuncAttributeMaxDynamicSharedMemorySize, SMEM_BYTES);
    inr_kernel<<<NCTA, 128, SMEM_BYTES>>>((const float4*)table, w1, w2, w3, (float*)d_out);
}

// round 9
// speedup vs baseline: 2.3260x; 1.0532x over previous
#include <cuda_runtime.h>
#include <cuda_fp16.h>
#include <stdint.h>

// ---------------------------------------------------------------------------
// TCNN INR fused: hash-grid encoding + MLP 48->128->128->1, fp16 HMMA path.
// Persistent grid (304 CTAs = 2/SM), 128-thread CTAs (M=64, 4 warps x 32 N).
// Software pipeline: next batch's encoding gathers issued under current
// batch's GEMM2 (double-buffered X tile). Weights persistent in registers.
// Encodings scaled by 2^14 to dodge fp16 subnormals (undone in epilogue).
// ---------------------------------------------------------------------------

#define NBATCH 16384           // 1024*1024 / 64 pixels per batch
#define NCTA 304               // 2 per SM, grid-stride over batches
#define SCALE 16384.0f
#define INV_SCALE (1.0f / 16384.0f)

#define XS_STRIDE_H 56         // 48 cols + pad (112B rows, 16B-aligned)
#define H1_STRIDE_H 136        // 128 cols + pad (272B rows, 16B-aligned)
#define SM_X_BYTES (64 * XS_STRIDE_H * 2)     // 7168 (x2 buffers)
#define SM_H1_BYTES (64 * H1_STRIDE_H * 2)    // 17408
#define SM_PART_BYTES (4 * 64 * 4)            // 1024
#define SMEM_BYTES (2 * SM_X_BYTES + SM_H1_BYTES + SM_PART_BYTES)

__constant__ float c_scale[12] = {
    15.0f, 23.0f, 35.0f, 53.0f, 80.0f, 120.5f, 181.25f, 272.375f,
    409.0625f, 614.09375f, 921.640625f, 1382.9609375f};
__constant__ uint32_t c_res[12] = {16, 24, 36, 54, 81, 122, 183, 274, 411, 616, 923, 1384};

static __device__ __forceinline__ uint32_t packh2(float lo, float hi) {
    __half2 h = __floats2half2_rn(lo, hi);
    return *(uint32_t*)&h;
}

static __device__ __forceinline__ void mma16(float d[4], const uint32_t a[4], const uint32_t b[2]) {
    asm volatile(
        "mma.sync.aligned.m16n8k16.row.col.f32.f16.f16.f32 "
        "{%0,%1,%2,%3}, {%4,%5,%6,%7}, {%8,%9}, {%0,%1,%2,%3};"
        : "+f"(d[0]), "+f"(d[1]), "+f"(d[2]), "+f"(d[3])
        : "r"(a[0]), "r"(a[1]), "r"(a[2]), "r"(a[3]), "r"(b[0]), "r"(b[1]));
}

#define LDSM_X4(r, addr) \
    asm volatile("ldmatrix.sync.aligned.m8n8.x4.shared.b16 {%0,%1,%2,%3}, [%4];" \
        : "=r"((r)[0]), "=r"((r)[1]), "=r"((r)[2]), "=r"((r)[3]) : "r"(addr))

#define STSM_X4(addr, r0, r1, r2, r3) \
    asm volatile("stmatrix.sync.aligned.m8n8.x4.shared.b16 [%0], {%1,%2,%3,%4};" \
        :: "r"(addr), "r"(r0), "r"(r1), "r"(r2), "r"(r3) : "memory")

// one 3-level encoding chunk held in registers between gather and interp
struct EncChunk {
    float4 t[3][4];
    float wx[3], wy[3];
};

static __device__ __forceinline__ void enc_gather(
    int lb, float fx, float fy, const float4* __restrict__ tab, EncChunk& c)
{
#pragma unroll
    for (int j = 0; j < 3; j++) {
        const int l = lb + j;
        const float s = c_scale[l];
        const uint32_t R = c_res[l];
        float px = fx * s + 0.5f, py = fy * s + 0.5f;
        float fpx = floorf(px), fpy = floorf(py);
        c.wx[j] = px - fpx; c.wy[j] = py - fpy;
        uint32_t ux = (uint32_t)fpx, uy = (uint32_t)fpy;
        uint32_t x0 = min(ux, R - 1u), x1 = min(ux + 1u, R - 1u);
        uint32_t y0 = min(uy, R - 1u), y1 = min(uy + 1u, R - 1u);
        uint32_t i00, i10, i01, i11;
        if (l < 11) {
            i00 = x0 + y0 * R; i10 = x1 + y0 * R;
            i01 = x0 + y1 * R; i11 = x1 + y1 * R;
        } else {
            uint32_t h0 = y0 * 2654435761u, h1 = y1 * 2654435761u;
            i00 = (x0 ^ h0) & 0xFFFFFu; i10 = (x1 ^ h0) & 0xFFFFFu;
            i01 = (x0 ^ h1) & 0xFFFFFu; i11 = (x1 ^ h1) & 0xFFFFFu;
        }
        const float4* base = tab + ((size_t)l << 20);
        c.t[j][0] = __ldg(base + i00);
        c.t[j][1] = __ldg(base + i10);
        c.t[j][2] = __ldg(base + i01);
        c.t[j][3] = __ldg(base + i11);
    }
}

static __device__ __forceinline__ void enc_store(int lb, const EncChunk& c, uint2* dst)
{
#pragma unroll
    for (int j = 0; j < 3; j++) {
        float wx = c.wx[j], wy = c.wy[j];
        float w00 = (1.f - wx) * (1.f - wy) * SCALE, w10 = wx * (1.f - wy) * SCALE;
        float w01 = (1.f - wx) * wy * SCALE,         w11 = wx * wy * SCALE;
        float e0 = c.t[j][0].x * w00 + c.t[j][1].x * w10 + c.t[j][2].x * w01 + c.t[j][3].x * w11;
        float e1 = c.t[j][0].y * w00 + c.t[j][1].y * w10 + c.t[j][2].y * w01 + c.t[j][3].y * w11;
        float e2 = c.t[j][0].z * w00 + c.t[j][1].z * w10 + c.t[j][2].z * w01 + c.t[j][3].z * w11;
        float e3 = c.t[j][0].w * w00 + c.t[j][1].w * w10 + c.t[j][2].w * w01 + c.t[j][3].w * w11;
        uint2 v;
        v.x = packh2(e0, e1);
        v.y = packh2(e2, e3);
        dst[lb + j] = v;
    }
}

__global__ __launch_bounds__(128, 2) void inr_kernel(
    const float4* __restrict__ tab,   // [12][2^20] float4
    const float* __restrict__ w1,     // [48][128]
    const float* __restrict__ w2,     // [128][128]
    const float* __restrict__ w3,     // [128]
    float* __restrict__ out)          // [1024*1024]
{
    extern __shared__ char smem[];
    __half* X0 = (__half*)smem;                        // [64][56] buffer 0
    __half* X1 = (__half*)(smem + SM_X_BYTES);         // [64][56] buffer 1
    __half* H1h = (__half*)(smem + 2 * SM_X_BYTES);    // [64][136]
    float* part = (float*)(smem + 2 * SM_X_BYTES + SM_H1_BYTES);

    const uint32_t Xu0 = (uint32_t)__cvta_generic_to_shared(X0);
    const uint32_t Xu1 = (uint32_t)__cvta_generic_to_shared(X1);
    const uint32_t H1u = (uint32_t)__cvta_generic_to_shared(H1h);

    const int tid = threadIdx.x;
    const int lane = tid & 31, ng = tid >> 5;   // warp = N-group (32 cols)
    const int q = lane & 3, ln4 = lane >> 2;
    const int lrow = lane & 15;
    const int lcol = (lane >> 4) << 3;

    // ---- persistent B fragments (weights), loaded once per CTA ----
    uint32_t B1[3][4][2];
    uint32_t B2[8][4][2];
#pragma unroll
    for (int s = 0; s < 3; s++)
#pragma unroll
        for (int nt = 0; nt < 4; nt++) {
            int kb = s * 16 + 2 * q;
            int n = ng * 32 + nt * 8 + ln4;
            B1[s][nt][0] = packh2(w1[(kb + 0) * 128 + n], w1[(kb + 1) * 128 + n]);
            B1[s][nt][1] = packh2(w1[(kb + 8) * 128 + n], w1[(kb + 9) * 128 + n]);
        }
#pragma unroll
    for (int s = 0; s < 8; s++)
#pragma unroll
        for (int nt = 0; nt < 4; nt++) {
            int kb = s * 16 + 2 * q;
            int n = ng * 32 + nt * 8 + ln4;
            B2[s][nt][0] = packh2(w2[(kb + 0) * 128 + n], w2[(kb + 1) * 128 + n]);
            B2[s][nt][1] = packh2(w2[(kb + 8) * 128 + n], w2[(kb + 9) * 128 + n]);
        }

    const uint32_t xfrag_off = (uint32_t)(lrow * XS_STRIDE_H + lcol) * 2;
    const uint32_t h1lda = H1u + (uint32_t)(lrow * H1_STRIDE_H + lcol) * 2;
    const uint32_t h1sta = H1u + (uint32_t)(lrow * H1_STRIDE_H + ng * 32 + lcol) * 2;

    const int r = tid >> 1;                 // encoded pixel row 0..63
    const int l0 = (tid & 1) * 6;           // this thread's 6-level window

    // ---- prologue: encode first batch into X0 ----
    {
        const int pix = blockIdx.x * 64 + r;
        const float fx = (float)(pix & 1023) * (1.0f / 1023.0f);
        const float fy = (float)(pix >> 10) * (1.0f / 1023.0f);
        uint2* dst = (uint2*)(X0 + r * XS_STRIDE_H);
        EncChunk c;
        enc_gather(l0, fx, fy, tab, c);
        enc_store(l0, c, dst);
        enc_gather(l0 + 3, fx, fy, tab, c);
        enc_store(l0 + 3, c, dst);
    }
    __syncthreads();

    int p = 0;
    for (int b = blockIdx.x; b < NBATCH; b += NCTA) {
        const uint32_t xlda = (p ? Xu1 : Xu0) + xfrag_off;
        uint2* xdstn = (uint2*)((p ? X0 : X1) + r * XS_STRIDE_H);  // next buffer
        // next batch coords (out-of-range prefetch on last iter is clamped/safe)
        const int pnx = (b + NCTA) * 64 + r;
        const float nfx = (float)(pnx & 1023) * (1.0f / 1023.0f);
        const float nfy = (float)(pnx >> 10) * (1.0f / 1023.0f);

        // ---------------- GEMM1: H1 = relu(X @ W1), M=64 --------------------
        float acc[4][4][4];
#pragma unroll
        for (int mt = 0; mt < 4; mt++)
#pragma unroll
            for (int nt = 0; nt < 4; nt++) {
                acc[mt][nt][0] = 0.f; acc[mt][nt][1] = 0.f;
                acc[mt][nt][2] = 0.f; acc[mt][nt][3] = 0.f;
            }
#pragma unroll
        for (int s = 0; s < 3; s++) {
            uint32_t a[4][4];
#pragma unroll
            for (int mt = 0; mt < 4; mt++)
                LDSM_X4(a[mt], xlda + (uint32_t)(mt * 16 * XS_STRIDE_H * 2 + s * 32));
#pragma unroll
            for (int mt = 0; mt < 4; mt++)
#pragma unroll
                for (int nt = 0; nt < 4; nt++)
                    mma16(acc[mt][nt], a[mt], B1[s][nt]);
        }

        // prefetch chunk0 of next batch (latency hides under STSM+sync+GEMM2a)
        EncChunk c0;
        enc_gather(l0, nfx, nfy, tab, c0);

        // relu -> fp16 -> H1 smem via stmatrix
#pragma unroll
        for (int mt = 0; mt < 4; mt++) {
            uint32_t v[4][2];
#pragma unroll
            for (int nt = 0; nt < 4; nt++) {
                v[nt][0] = packh2(fmaxf(acc[mt][nt][0], 0.f), fmaxf(acc[mt][nt][1], 0.f));
                v[nt][1] = packh2(fmaxf(acc[mt][nt][2], 0.f), fmaxf(acc[mt][nt][3], 0.f));
            }
            uint32_t sa = h1sta + (uint32_t)(mt * 16 * H1_STRIDE_H * 2);
            STSM_X4(sa, v[0][0], v[0][1], v[1][0], v[1][1]);
            STSM_X4(sa + 32, v[2][0], v[2][1], v[3][0], v[3][1]);
        }
        __syncthreads();

        // ---------------- GEMM2 first half: s = 0..3 ------------------------
#pragma unroll
        for (int mt = 0; mt < 4; mt++)
#pragma unroll
            for (int nt = 0; nt < 4; nt++) {
                acc[mt][nt][0] = 0.f; acc[mt][nt][1] = 0.f;
                acc[mt][nt][2] = 0.f; acc[mt][nt][3] = 0.f;
            }
#pragma unroll
        for (int s = 0; s < 4; s++) {
            uint32_t a[4][4];
#pragma unroll
            for (int mt = 0; mt < 4; mt++)
                LDSM_X4(a[mt], h1lda + (uint32_t)(mt * 16 * H1_STRIDE_H * 2 + s * 32));
#pragma unroll
            for (int mt = 0; mt < 4; mt++)
#pragma unroll
                for (int nt = 0; nt < 4; nt++)
                    mma16(acc[mt][nt], a[mt], B2[s][nt]);
        }

        // chunk0 interp+store to next X buffer; issue chunk1 gathers
        enc_store(l0, c0, xdstn);
        EncChunk c1;
        enc_gather(l0 + 3, nfx, nfy, tab, c1);

        // ---------------- GEMM2 second half: s = 4..7 -----------------------
#pragma unroll
        for (int s = 4; s < 8; s++) {
            uint32_t a[4][4];
#pragma unroll
            for (int mt = 0; mt < 4; mt++)
                LDSM_X4(a[mt], h1lda + (uint32_t)(mt * 16 * H1_STRIDE_H * 2 + s * 32));
#pragma unroll
            for (int mt = 0; mt < 4; mt++)
#pragma unroll
                for (int nt = 0; nt < 4; nt++)
                    mma16(acc[mt][nt], a[mt], B2[s][nt]);
        }

        // ---------------- epilogue: partial relu(H2).w3 per N-group ---------
        {
            float w3a[4], w3b[4];
#pragma unroll
            for (int nt = 0; nt < 4; nt++) {
                w3a[nt] = __ldg(w3 + ng * 32 + nt * 8 + 2 * q);
                w3b[nt] = __ldg(w3 + ng * 32 + nt * 8 + 2 * q + 1);
            }
#pragma unroll
            for (int mt = 0; mt < 4; mt++) {
                float s0 = 0.f, s1 = 0.f;
#pragma unroll
                for (int nt = 0; nt < 4; nt++) {
                    s0 += fmaxf(acc[mt][nt][0], 0.f) * w3a[nt] + fmaxf(acc[mt][nt][1], 0.f) * w3b[nt];
                    s1 += fmaxf(acc[mt][nt][2], 0.f) * w3a[nt] + fmaxf(acc[mt][nt][3], 0.f) * w3b[nt];
                }
                s0 += __shfl_xor_sync(0xffffffffu, s0, 1);
                s0 += __shfl_xor_sync(0xffffffffu, s0, 2);
                s1 += __shfl_xor_sync(0xffffffffu, s1, 1);
                s1 += __shfl_xor_sync(0xffffffffu, s1, 2);
                if (q == 0) {
                    int r0 = mt * 16 + ln4;
                    part[ng * 64 + r0] = s0;
                    part[ng * 64 + r0 + 8] = s1;
                }
            }
        }
        __syncthreads();

        if (tid < 64) {
            float o = (part[tid] + part[64 + tid] + part[128 + tid] + part[192 + tid]) * INV_SCALE;
            out[b * 64 + tid] = o;
        }
        // chunk1 interp+store to next X buffer, then publish for next GEMM1
        enc_store(l0 + 3, c1, xdstn);
        __syncthreads();
        p ^= 1;
    }
}

extern "C" void kernel_launch(void* const* d_in, const int* in_sizes, int n_in,
                              void* d_out, int out_size) {
    const float* table = nullptr;
    const float* w1 = nullptr;
    const float* w2 = nullptr;
    const float* w3 = nullptr;
    for (int i = 0; i < n_in; i++) {
        switch (in_sizes[i]) {
            case 12 * 1048576 * 4: table = (const float*)d_in[i]; break;
            case 48 * 128:         w1 = (const float*)d_in[i]; break;
            case 128 * 128:        w2 = (const float*)d_in[i]; break;
            case 128:              w3 = (const float*)d_in[i]; break;
            default: break;
        }
    }
    if (!table) table = (const float*)d_in[2];
    if (!w1) w1 = (const float*)d_in[3];
    if (!w2) w2 = (const float*)d_in[4];
    if (!w3) w3 = (const float*)d_in[5];

    cudaFuncSetAttribute(inr_kernel, cudaFuncAttributeMaxDynamicSharedMemorySize, SMEM_BYTES);
    inr_kernel<<<NCTA, 128, SMEM_BYTES>>>((const float4*)table, w1, w2, w3, (float*)d_out);
}

// round 10
// speedup vs baseline: 2.4184x; 1.0397x over previous
#include <cuda_runtime.h>
#include <cuda_fp16.h>
#include <stdint.h>

// ---------------------------------------------------------------------------
// TCNN INR fused: hash-grid encoding + MLP 48->128->128->1, fp16 HMMA path.
// Persistent grid (304 CTAs = 2/SM), 128-thread CTAs (M=64, 4 warps x 32 N).
// Software pipeline: next batch's encoding gathers issued in 3 small chunks
// (2 levels each) under the current batch's GEMM2 (double-buffered X tile).
// Weights persistent in registers. Encodings scaled by 2^14 vs fp16 denorms.
// ---------------------------------------------------------------------------

#define NBATCH 16384           // 1024*1024 / 64 pixels per batch
#define NCTA 304               // 2 per SM, grid-stride over batches
#define SCALE 16384.0f
#define INV_SCALE (1.0f / 16384.0f)

#define XS_STRIDE_H 56         // 48 cols + pad (112B rows, 16B-aligned)
#define H1_STRIDE_H 136        // 128 cols + pad (272B rows, 16B-aligned)
#define SM_X_BYTES (64 * XS_STRIDE_H * 2)     // 7168 (x2 buffers)
#define SM_H1_BYTES (64 * H1_STRIDE_H * 2)    // 17408
#define SM_PART_BYTES (4 * 64 * 4)            // 1024
#define SMEM_BYTES (2 * SM_X_BYTES + SM_H1_BYTES + SM_PART_BYTES)

__constant__ float c_scale[12] = {
    15.0f, 23.0f, 35.0f, 53.0f, 80.0f, 120.5f, 181.25f, 272.375f,
    409.0625f, 614.09375f, 921.640625f, 1382.9609375f};
__constant__ uint32_t c_res[12] = {16, 24, 36, 54, 81, 122, 183, 274, 411, 616, 923, 1384};

static __device__ __forceinline__ uint32_t packh2(float lo, float hi) {
    __half2 h = __floats2half2_rn(lo, hi);
    return *(uint32_t*)&h;
}

static __device__ __forceinline__ void mma16(float d[4], const uint32_t a[4], const uint32_t b[2]) {
    asm volatile(
        "mma.sync.aligned.m16n8k16.row.col.f32.f16.f16.f32 "
        "{%0,%1,%2,%3}, {%4,%5,%6,%7}, {%8,%9}, {%0,%1,%2,%3};"
        : "+f"(d[0]), "+f"(d[1]), "+f"(d[2]), "+f"(d[3])
        : "r"(a[0]), "r"(a[1]), "r"(a[2]), "r"(a[3]), "r"(b[0]), "r"(b[1]));
}

#define LDSM_X4(r, addr) \
    asm volatile("ldmatrix.sync.aligned.m8n8.x4.shared.b16 {%0,%1,%2,%3}, [%4];" \
        : "=r"((r)[0]), "=r"((r)[1]), "=r"((r)[2]), "=r"((r)[3]) : "r"(addr))

#define STSM_X4(addr, r0, r1, r2, r3) \
    asm volatile("stmatrix.sync.aligned.m8n8.x4.shared.b16 [%0], {%1,%2,%3,%4};" \
        :: "r"(addr), "r"(r0), "r"(r1), "r"(r2), "r"(r3) : "memory")

// one 2-level encoding chunk held in registers between gather and interp
struct EncChunk2 {
    float4 t[2][4];
    float wx[2], wy[2];
};

static __device__ __forceinline__ void enc_gather2(
    int lb, float fx, float fy, const float4* __restrict__ tab, EncChunk2& c)
{
#pragma unroll
    for (int j = 0; j < 2; j++) {
        const int l = lb + j;
        const float s = c_scale[l];
        const uint32_t R = c_res[l];
        float px = fx * s + 0.5f, py = fy * s + 0.5f;
        float fpx = floorf(px), fpy = floorf(py);
        c.wx[j] = px - fpx; c.wy[j] = py - fpy;
        uint32_t ux = (uint32_t)fpx, uy = (uint32_t)fpy;
        uint32_t x0 = min(ux, R - 1u), x1 = min(ux + 1u, R - 1u);
        uint32_t y0 = min(uy, R - 1u), y1 = min(uy + 1u, R - 1u);
        uint32_t i00, i10, i01, i11;
        if (l < 11) {
            i00 = x0 + y0 * R; i10 = x1 + y0 * R;
            i01 = x0 + y1 * R; i11 = x1 + y1 * R;
        } else {
            uint32_t h0 = y0 * 2654435761u, h1 = y1 * 2654435761u;
            i00 = (x0 ^ h0) & 0xFFFFFu; i10 = (x1 ^ h0) & 0xFFFFFu;
            i01 = (x0 ^ h1) & 0xFFFFFu; i11 = (x1 ^ h1) & 0xFFFFFu;
        }
        const float4* base = tab + ((size_t)l << 20);
        c.t[j][0] = __ldg(base + i00);
        c.t[j][1] = __ldg(base + i10);
        c.t[j][2] = __ldg(base + i01);
        c.t[j][3] = __ldg(base + i11);
    }
}

static __device__ __forceinline__ void enc_store2(int lb, const EncChunk2& c, uint2* dst)
{
#pragma unroll
    for (int j = 0; j < 2; j++) {
        float wx = c.wx[j], wy = c.wy[j];
        float w00 = (1.f - wx) * (1.f - wy) * SCALE, w10 = wx * (1.f - wy) * SCALE;
        float w01 = (1.f - wx) * wy * SCALE,         w11 = wx * wy * SCALE;
        float e0 = c.t[j][0].x * w00 + c.t[j][1].x * w10 + c.t[j][2].x * w01 + c.t[j][3].x * w11;
        float e1 = c.t[j][0].y * w00 + c.t[j][1].y * w10 + c.t[j][2].y * w01 + c.t[j][3].y * w11;
        float e2 = c.t[j][0].z * w00 + c.t[j][1].z * w10 + c.t[j][2].z * w01 + c.t[j][3].z * w11;
        float e3 = c.t[j][0].w * w00 + c.t[j][1].w * w10 + c.t[j][2].w * w01 + c.t[j][3].w * w11;
        uint2 v;
        v.x = packh2(e0, e1);
        v.y = packh2(e2, e3);
        dst[lb + j] = v;
    }
}

__global__ __launch_bounds__(128, 2) void inr_kernel(
    const float4* __restrict__ tab,   // [12][2^20] float4
    const float* __restrict__ w1,     // [48][128]
    const float* __restrict__ w2,     // [128][128]
    const float* __restrict__ w3,     // [128]
    float* __restrict__ out)          // [1024*1024]
{
    extern __shared__ char smem[];
    __half* X0 = (__half*)smem;                        // [64][56] buffer 0
    __half* X1 = (__half*)(smem + SM_X_BYTES);         // [64][56] buffer 1
    __half* H1h = (__half*)(smem + 2 * SM_X_BYTES);    // [64][136]
    float* part = (float*)(smem + 2 * SM_X_BYTES + SM_H1_BYTES);

    const uint32_t Xu0 = (uint32_t)__cvta_generic_to_shared(X0);
    const uint32_t Xu1 = (uint32_t)__cvta_generic_to_shared(X1);
    const uint32_t H1u = (uint32_t)__cvta_generic_to_shared(H1h);

    const int tid = threadIdx.x;
    const int lane = tid & 31, ng = tid >> 5;   // warp = N-group (32 cols)
    const int q = lane & 3, ln4 = lane >> 2;
    const int lrow = lane & 15;
    const int lcol = (lane >> 4) << 3;

    // ---- persistent B fragments (weights), loaded once per CTA ----
    uint32_t B1[3][4][2];
    uint32_t B2[8][4][2];
#pragma unroll
    for (int s = 0; s < 3; s++)
#pragma unroll
        for (int nt = 0; nt < 4; nt++) {
            int kb = s * 16 + 2 * q;
            int n = ng * 32 + nt * 8 + ln4;
            B1[s][nt][0] = packh2(w1[(kb + 0) * 128 + n], w1[(kb + 1) * 128 + n]);
            B1[s][nt][1] = packh2(w1[(kb + 8) * 128 + n], w1[(kb + 9) * 128 + n]);
        }
#pragma unroll
    for (int s = 0; s < 8; s++)
#pragma unroll
        for (int nt = 0; nt < 4; nt++) {
            int kb = s * 16 + 2 * q;
            int n = ng * 32 + nt * 8 + ln4;
            B2[s][nt][0] = packh2(w2[(kb + 0) * 128 + n], w2[(kb + 1) * 128 + n]);
            B2[s][nt][1] = packh2(w2[(kb + 8) * 128 + n], w2[(kb + 9) * 128 + n]);
        }

    const uint32_t xfrag_off = (uint32_t)(lrow * XS_STRIDE_H + lcol) * 2;
    const uint32_t h1lda = H1u + (uint32_t)(lrow * H1_STRIDE_H + lcol) * 2;
    const uint32_t h1sta = H1u + (uint32_t)(lrow * H1_STRIDE_H + ng * 32 + lcol) * 2;

    const int r = tid >> 1;                 // encoded pixel row 0..63
    const int l0 = (tid & 1) * 6;           // this thread's 6-level window

    // ---- prologue: encode first batch into X0 ----
    {
        const int pix = blockIdx.x * 64 + r;
        const float fx = (float)(pix & 1023) * (1.0f / 1023.0f);
        const float fy = (float)(pix >> 10) * (1.0f / 1023.0f);
        uint2* dst = (uint2*)(X0 + r * XS_STRIDE_H);
        EncChunk2 c;
#pragma unroll
        for (int k = 0; k < 3; k++) {
            enc_gather2(l0 + 2 * k, fx, fy, tab, c);
            enc_store2(l0 + 2 * k, c, dst);
        }
    }
    __syncthreads();

    int p = 0;
    for (int b = blockIdx.x; b < NBATCH; b += NCTA) {
        const uint32_t xlda = (p ? Xu1 : Xu0) + xfrag_off;
        uint2* xdstn = (uint2*)((p ? X0 : X1) + r * XS_STRIDE_H);  // next buffer
        // next batch coords (out-of-range prefetch on last iter is clamped/safe)
        const int pnx = (b + NCTA) * 64 + r;
        const float nfx = (float)(pnx & 1023) * (1.0f / 1023.0f);
        const float nfy = (float)(pnx >> 10) * (1.0f / 1023.0f);

        // ---------------- GEMM1: H1 = relu(X @ W1), M=64 --------------------
        float acc[4][4][4];
#pragma unroll
        for (int mt = 0; mt < 4; mt++)
#pragma unroll
            for (int nt = 0; nt < 4; nt++) {
                acc[mt][nt][0] = 0.f; acc[mt][nt][1] = 0.f;
                acc[mt][nt][2] = 0.f; acc[mt][nt][3] = 0.f;
            }
#pragma unroll
        for (int s = 0; s < 3; s++) {
            uint32_t a[4][4];
#pragma unroll
            for (int mt = 0; mt < 4; mt++)
                LDSM_X4(a[mt], xlda + (uint32_t)(mt * 16 * XS_STRIDE_H * 2 + s * 32));
#pragma unroll
            for (int mt = 0; mt < 4; mt++)
#pragma unroll
                for (int nt = 0; nt < 4; nt++)
                    mma16(acc[mt][nt], a[mt], B1[s][nt]);
        }

        // prefetch chunk0 of next batch (hides under STSM + sync + GEMM2 s0-2)
        EncChunk2 ec;
        enc_gather2(l0, nfx, nfy, tab, ec);

        // relu -> fp16 -> H1 smem via stmatrix
#pragma unroll
        for (int mt = 0; mt < 4; mt++) {
            uint32_t v[4][2];
#pragma unroll
            for (int nt = 0; nt < 4; nt++) {
                v[nt][0] = packh2(fmaxf(acc[mt][nt][0], 0.f), fmaxf(acc[mt][nt][1], 0.f));
                v[nt][1] = packh2(fmaxf(acc[mt][nt][2], 0.f), fmaxf(acc[mt][nt][3], 0.f));
            }
            uint32_t sa = h1sta + (uint32_t)(mt * 16 * H1_STRIDE_H * 2);
            STSM_X4(sa, v[0][0], v[0][1], v[1][0], v[1][1]);
            STSM_X4(sa + 32, v[2][0], v[2][1], v[3][0], v[3][1]);
        }
        __syncthreads();

        // ---------------- GEMM2: s = 0..2 -----------------------------------
#pragma unroll
        for (int mt = 0; mt < 4; mt++)
#pragma unroll
            for (int nt = 0; nt < 4; nt++) {
                acc[mt][nt][0] = 0.f; acc[mt][nt][1] = 0.f;
                acc[mt][nt][2] = 0.f; acc[mt][nt][3] = 0.f;
            }
#pragma unroll
        for (int s = 0; s < 3; s++) {
            uint32_t a[4][4];
#pragma unroll
            for (int mt = 0; mt < 4; mt++)
                LDSM_X4(a[mt], h1lda + (uint32_t)(mt * 16 * H1_STRIDE_H * 2 + s * 32));
#pragma unroll
            for (int mt = 0; mt < 4; mt++)
#pragma unroll
                for (int nt = 0; nt < 4; nt++)
                    mma16(acc[mt][nt], a[mt], B2[s][nt]);
        }

        // chunk0 -> next X buffer; issue chunk1 gathers
        enc_store2(l0, ec, xdstn);
        enc_gather2(l0 + 2, nfx, nfy, tab, ec);

        // ---------------- GEMM2: s = 3..5 -----------------------------------
#pragma unroll
        for (int s = 3; s < 6; s++) {
            uint32_t a[4][4];
#pragma unroll
            for (int mt = 0; mt < 4; mt++)
                LDSM_X4(a[mt], h1lda + (uint32_t)(mt * 16 * H1_STRIDE_H * 2 + s * 32));
#pragma unroll
            for (int mt = 0; mt < 4; mt++)
#pragma unroll
                for (int nt = 0; nt < 4; nt++)
                    mma16(acc[mt][nt], a[mt], B2[s][nt]);
        }

        // chunk1 -> next X buffer; issue chunk2 gathers
        enc_store2(l0 + 2, ec, xdstn);
        enc_gather2(l0 + 4, nfx, nfy, tab, ec);

        // ---------------- GEMM2: s = 6..7 -----------------------------------
#pragma unroll
        for (int s = 6; s < 8; s++) {
            uint32_t a[4][4];
#pragma unroll
            for (int mt = 0; mt < 4; mt++)
                LDSM_X4(a[mt], h1lda + (uint32_t)(mt * 16 * H1_STRIDE_H * 2 + s * 32));
#pragma unroll
            for (int mt = 0; mt < 4; mt++)
#pragma unroll
                for (int nt = 0; nt < 4; nt++)
                    mma16(acc[mt][nt], a[mt], B2[s][nt]);
        }

        // ---------------- epilogue: partial relu(H2).w3 per N-group ---------
        {
            float w3a[4], w3b[4];
#pragma unroll
            for (int nt = 0; nt < 4; nt++) {
                w3a[nt] = __ldg(w3 + ng * 32 + nt * 8 + 2 * q);
                w3b[nt] = __ldg(w3 + ng * 32 + nt * 8 + 2 * q + 1);
            }
#pragma unroll
            for (int mt = 0; mt < 4; mt++) {
                float s0 = 0.f, s1 = 0.f;
#pragma unroll
                for (int nt = 0; nt < 4; nt++) {
                    s0 += fmaxf(acc[mt][nt][0], 0.f) * w3a[nt] + fmaxf(acc[mt][nt][1], 0.f) * w3b[nt];
                    s1 += fmaxf(acc[mt][nt][2], 0.f) * w3a[nt] + fmaxf(acc[mt][nt][3], 0.f) * w3b[nt];
                }
                s0 += __shfl_xor_sync(0xffffffffu, s0, 1);
                s0 += __shfl_xor_sync(0xffffffffu, s0, 2);
                s1 += __shfl_xor_sync(0xffffffffu, s1, 1);
                s1 += __shfl_xor_sync(0xffffffffu, s1, 2);
                if (q == 0) {
                    int r0 = mt * 16 + ln4;
                    part[ng * 64 + r0] = s0;
                    part[ng * 64 + r0 + 8] = s1;
                }
            }
        }
        __syncthreads();

        if (tid < 64) {
            float o = (part[tid] + part[64 + tid] + part[128 + tid] + part[192 + tid]) * INV_SCALE;
            out[b * 64 + tid] = o;
        }
        // chunk2 -> next X buffer, then publish for next GEMM1
        enc_store2(l0 + 4, ec, xdstn);
        __syncthreads();
        p ^= 1;
    }
}

extern "C" void kernel_launch(void* const* d_in, const int* in_sizes, int n_in,
                              void* d_out, int out_size) {
    const float* table = nullptr;
    const float* w1 = nullptr;
    const float* w2 = nullptr;
    const float* w3 = nullptr;
    for (int i = 0; i < n_in; i++) {
        switch (in_sizes[i]) {
            case 12 * 1048576 * 4: table = (const float*)d_in[i]; break;
            case 48 * 128:         w1 = (const float*)d_in[i]; break;
            case 128 * 128:        w2 = (const float*)d_in[i]; break;
            case 128:              w3 = (const float*)d_in[i]; break;
            default: break;
        }
    }
    if (!table) table = (const float*)d_in[2];
    if (!w1) w1 = (const float*)d_in[3];
    if (!w2) w2 = (const float*)d_in[4];
    if (!w3) w3 = (const float*)d_in[5];

    cudaFuncSetAttribute(inr_kernel, cudaFuncAttributeMaxDynamicSharedMemorySize, SMEM_BYTES);
    inr_kernel<<<NCTA, 128, SMEM_BYTES>>>((const float4*)table, w1, w2, w3, (float*)d_out);
}

// round 11
// speedup vs baseline: 2.4993x; 1.0335x over previous
#include <cuda_runtime.h>
#include <cuda_fp16.h>
#include <stdint.h>

// ---------------------------------------------------------------------------
// TCNN INR fused: hash-grid encoding + MLP 48->128->128->1, fp16 HMMA path.
// Persistent grid (304 CTAs = 2/SM), 128-thread CTAs (M=64, 4 warps x 32 N).
// Encoding lane map is warp-uniform in LEVEL (warp&1 -> pixel half, warp>>1 ->
// levelset), so every table-gather instruction touches one level with 32
// consecutive pixels -> few L1 wavefronts. 3-chunk software pipeline issues
// next batch's gathers under current GEMM2 (double-buffered X tile).
// Weights persistent in registers. Encodings scaled by 2^14 vs fp16 denorms.
// ---------------------------------------------------------------------------

#define NBATCH 16384           // 1024*1024 / 64 pixels per batch
#define NCTA 304               // 2 per SM, grid-stride over batches
#define SCALE 16384.0f
#define INV_SCALE (1.0f / 16384.0f)

#define XS_STRIDE_H 56         // 48 cols + pad (112B rows, 16B-aligned)
#define H1_STRIDE_H 136        // 128 cols + pad (272B rows, 16B-aligned)
#define SM_X_BYTES (64 * XS_STRIDE_H * 2)     // 7168 (x2 buffers)
#define SM_H1_BYTES (64 * H1_STRIDE_H * 2)    // 17408
#define SM_PART_BYTES (4 * 64 * 4)            // 1024
#define SMEM_BYTES (2 * SM_X_BYTES + SM_H1_BYTES + SM_PART_BYTES)

__constant__ float c_scale[12] = {
    15.0f, 23.0f, 35.0f, 53.0f, 80.0f, 120.5f, 181.25f, 272.375f,
    409.0625f, 614.09375f, 921.640625f, 1382.9609375f};
__constant__ uint32_t c_res[12] = {16, 24, 36, 54, 81, 122, 183, 274, 411, 616, 923, 1384};

static __device__ __forceinline__ uint32_t packh2(float lo, float hi) {
    __half2 h = __floats2half2_rn(lo, hi);
    return *(uint32_t*)&h;
}

static __device__ __forceinline__ void mma16(float d[4], const uint32_t a[4], const uint32_t b[2]) {
    asm volatile(
        "mma.sync.aligned.m16n8k16.row.col.f32.f16.f16.f32 "
        "{%0,%1,%2,%3}, {%4,%5,%6,%7}, {%8,%9}, {%0,%1,%2,%3};"
        : "+f"(d[0]), "+f"(d[1]), "+f"(d[2]), "+f"(d[3])
        : "r"(a[0]), "r"(a[1]), "r"(a[2]), "r"(a[3]), "r"(b[0]), "r"(b[1]));
}

#define LDSM_X4(r, addr) \
    asm volatile("ldmatrix.sync.aligned.m8n8.x4.shared.b16 {%0,%1,%2,%3}, [%4];" \
        : "=r"((r)[0]), "=r"((r)[1]), "=r"((r)[2]), "=r"((r)[3]) : "r"(addr))

#define STSM_X4(addr, r0, r1, r2, r3) \
    asm volatile("stmatrix.sync.aligned.m8n8.x4.shared.b16 [%0], {%1,%2,%3,%4};" \
        :: "r"(addr), "r"(r0), "r"(r1), "r"(r2), "r"(r3) : "memory")

// one 2-level encoding chunk held in registers between gather and interp
struct EncChunk2 {
    float4 t[2][4];
    float wx[2], wy[2];
};

static __device__ __forceinline__ void enc_gather2(
    int lb, float fx, float fy, const float4* __restrict__ tab, EncChunk2& c)
{
#pragma unroll
    for (int j = 0; j < 2; j++) {
        const int l = lb + j;
        const float s = c_scale[l];
        const uint32_t R = c_res[l];
        float px = fx * s + 0.5f, py = fy * s + 0.5f;
        float fpx = floorf(px), fpy = floorf(py);
        c.wx[j] = px - fpx; c.wy[j] = py - fpy;
        uint32_t ux = (uint32_t)fpx, uy = (uint32_t)fpy;
        uint32_t x0 = min(ux, R - 1u), x1 = min(ux + 1u, R - 1u);
        uint32_t y0 = min(uy, R - 1u), y1 = min(uy + 1u, R - 1u);
        uint32_t i00, i10, i01, i11;
        if (l < 11) {
            i00 = x0 + y0 * R; i10 = x1 + y0 * R;
            i01 = x0 + y1 * R; i11 = x1 + y1 * R;
        } else {
            uint32_t h0 = y0 * 2654435761u, h1 = y1 * 2654435761u;
            i00 = (x0 ^ h0) & 0xFFFFFu; i10 = (x1 ^ h0) & 0xFFFFFu;
            i01 = (x0 ^ h1) & 0xFFFFFu; i11 = (x1 ^ h1) & 0xFFFFFu;
        }
        const float4* base = tab + ((size_t)l << 20);
        c.t[j][0] = __ldg(base + i00);
        c.t[j][1] = __ldg(base + i10);
        c.t[j][2] = __ldg(base + i01);
        c.t[j][3] = __ldg(base + i11);
    }
}

static __device__ __forceinline__ void enc_store2(int lb, const EncChunk2& c, uint2* dst)
{
#pragma unroll
    for (int j = 0; j < 2; j++) {
        float wx = c.wx[j], wy = c.wy[j];
        float w00 = (1.f - wx) * (1.f - wy) * SCALE, w10 = wx * (1.f - wy) * SCALE;
        float w01 = (1.f - wx) * wy * SCALE,         w11 = wx * wy * SCALE;
        float e0 = c.t[j][0].x * w00 + c.t[j][1].x * w10 + c.t[j][2].x * w01 + c.t[j][3].x * w11;
        float e1 = c.t[j][0].y * w00 + c.t[j][1].y * w10 + c.t[j][2].y * w01 + c.t[j][3].y * w11;
        float e2 = c.t[j][0].z * w00 + c.t[j][1].z * w10 + c.t[j][2].z * w01 + c.t[j][3].z * w11;
        float e3 = c.t[j][0].w * w00 + c.t[j][1].w * w10 + c.t[j][2].w * w01 + c.t[j][3].w * w11;
        uint2 v;
        v.x = packh2(e0, e1);
        v.y = packh2(e2, e3);
        dst[lb + j] = v;
    }
}

__global__ __launch_bounds__(128, 2) void inr_kernel(
    const float4* __restrict__ tab,   // [12][2^20] float4
    const float* __restrict__ w1,     // [48][128]
    const float* __restrict__ w2,     // [128][128]
    const float* __restrict__ w3,     // [128]
    float* __restrict__ out)          // [1024*1024]
{
    extern __shared__ char smem[];
    __half* X0 = (__half*)smem;                        // [64][56] buffer 0
    __half* X1 = (__half*)(smem + SM_X_BYTES);         // [64][56] buffer 1
    __half* H1h = (__half*)(smem + 2 * SM_X_BYTES);    // [64][136]
    float* part = (float*)(smem + 2 * SM_X_BYTES + SM_H1_BYTES);

    const uint32_t Xu0 = (uint32_t)__cvta_generic_to_shared(X0);
    const uint32_t Xu1 = (uint32_t)__cvta_generic_to_shared(X1);
    const uint32_t H1u = (uint32_t)__cvta_generic_to_shared(H1h);

    const int tid = threadIdx.x;
    const int lane = tid & 31, ng = tid >> 5;   // warp = N-group (32 cols)
    const int q = lane & 3, ln4 = lane >> 2;
    const int lrow = lane & 15;
    const int lcol = (lane >> 4) << 3;

    // ---- persistent B fragments (weights), loaded once per CTA ----
    uint32_t B1[3][4][2];
    uint32_t B2[8][4][2];
#pragma unroll
    for (int s = 0; s < 3; s++)
#pragma unroll
        for (int nt = 0; nt < 4; nt++) {
            int kb = s * 16 + 2 * q;
            int n = ng * 32 + nt * 8 + ln4;
            B1[s][nt][0] = packh2(w1[(kb + 0) * 128 + n], w1[(kb + 1) * 128 + n]);
            B1[s][nt][1] = packh2(w1[(kb + 8) * 128 + n], w1[(kb + 9) * 128 + n]);
        }
#pragma unroll
    for (int s = 0; s < 8; s++)
#pragma unroll
        for (int nt = 0; nt < 4; nt++) {
            int kb = s * 16 + 2 * q;
            int n = ng * 32 + nt * 8 + ln4;
            B2[s][nt][0] = packh2(w2[(kb + 0) * 128 + n], w2[(kb + 1) * 128 + n]);
            B2[s][nt][1] = packh2(w2[(kb + 8) * 128 + n], w2[(kb + 9) * 128 + n]);
        }

    const uint32_t xfrag_off = (uint32_t)(lrow * XS_STRIDE_H + lcol) * 2;
    const uint32_t h1lda = H1u + (uint32_t)(lrow * H1_STRIDE_H + lcol) * 2;
    const uint32_t h1sta = H1u + (uint32_t)(lrow * H1_STRIDE_H + ng * 32 + lcol) * 2;

    // encoding assignment: warp-uniform level, consecutive pixels per warp.
    // warps 0,1 -> levels 0..5 for pixel halves 0,1; warps 2,3 -> levels 6..11.
    const int er = ((ng & 1) << 5) | lane;   // pixel row 0..63
    const int el0 = (ng >> 1) * 6;           // this warp's 6-level window

    // ---- prologue: encode first batch into X0 ----
    {
        const int pix = blockIdx.x * 64 + er;
        const float fx = (float)(pix & 1023) * (1.0f / 1023.0f);
        const float fy = (float)(pix >> 10) * (1.0f / 1023.0f);
        uint2* dst = (uint2*)(X0 + er * XS_STRIDE_H);
        EncChunk2 c;
#pragma unroll
        for (int k = 0; k < 3; k++) {
            enc_gather2(el0 + 2 * k, fx, fy, tab, c);
            enc_store2(el0 + 2 * k, c, dst);
        }
    }
    __syncthreads();

    int p = 0;
    for (int b = blockIdx.x; b < NBATCH; b += NCTA) {
        const uint32_t xlda = (p ? Xu1 : Xu0) + xfrag_off;
        uint2* xdstn = (uint2*)((p ? X0 : X1) + er * XS_STRIDE_H);  // next buffer
        // next batch coords (out-of-range prefetch on last iter is clamped/safe)
        const int pnx = (b + NCTA) * 64 + er;
        const float nfx = (float)(pnx & 1023) * (1.0f / 1023.0f);
        const float nfy = (float)(pnx >> 10) * (1.0f / 1023.0f);

        // ---------------- GEMM1: H1 = relu(X @ W1), M=64 --------------------
        float acc[4][4][4];
#pragma unroll
        for (int mt = 0; mt < 4; mt++)
#pragma unroll
            for (int nt = 0; nt < 4; nt++) {
                acc[mt][nt][0] = 0.f; acc[mt][nt][1] = 0.f;
                acc[mt][nt][2] = 0.f; acc[mt][nt][3] = 0.f;
            }
#pragma unroll
        for (int s = 0; s < 3; s++) {
            uint32_t a[4][4];
#pragma unroll
            for (int mt = 0; mt < 4; mt++)
                LDSM_X4(a[mt], xlda + (uint32_t)(mt * 16 * XS_STRIDE_H * 2 + s * 32));
#pragma unroll
            for (int mt = 0; mt < 4; mt++)
#pragma unroll
                for (int nt = 0; nt < 4; nt++)
                    mma16(acc[mt][nt], a[mt], B1[s][nt]);
        }

        // prefetch chunk0 of next batch (hides under STSM + sync + GEMM2 s0-2)
        EncChunk2 ec;
        enc_gather2(el0, nfx, nfy, tab, ec);

        // relu -> fp16 -> H1 smem via stmatrix
#pragma unroll
        for (int mt = 0; mt < 4; mt++) {
            uint32_t v[4][2];
#pragma unroll
            for (int nt = 0; nt < 4; nt++) {
                v[nt][0] = packh2(fmaxf(acc[mt][nt][0], 0.f), fmaxf(acc[mt][nt][1], 0.f));
                v[nt][1] = packh2(fmaxf(acc[mt][nt][2], 0.f), fmaxf(acc[mt][nt][3], 0.f));
            }
            uint32_t sa = h1sta + (uint32_t)(mt * 16 * H1_STRIDE_H * 2);
            STSM_X4(sa, v[0][0], v[0][1], v[1][0], v[1][1]);
            STSM_X4(sa + 32, v[2][0], v[2][1], v[3][0], v[3][1]);
        }
        __syncthreads();

        // ---------------- GEMM2: s = 0..2 -----------------------------------
#pragma unroll
        for (int mt = 0; mt < 4; mt++)
#pragma unroll
            for (int nt = 0; nt < 4; nt++) {
                acc[mt][nt][0] = 0.f; acc[mt][nt][1] = 0.f;
                acc[mt][nt][2] = 0.f; acc[mt][nt][3] = 0.f;
            }
#pragma unroll
        for (int s = 0; s < 3; s++) {
            uint32_t a[4][4];
#pragma unroll
            for (int mt = 0; mt < 4; mt++)
                LDSM_X4(a[mt], h1lda + (uint32_t)(mt * 16 * H1_STRIDE_H * 2 + s * 32));
#pragma unroll
            for (int mt = 0; mt < 4; mt++)
#pragma unroll
                for (int nt = 0; nt < 4; nt++)
                    mma16(acc[mt][nt], a[mt], B2[s][nt]);
        }

        // chunk0 -> next X buffer; issue chunk1 gathers
        enc_store2(el0, ec, xdstn);
        enc_gather2(el0 + 2, nfx, nfy, tab, ec);

        // ---------------- GEMM2: s = 3..5 -----------------------------------
#pragma unroll
        for (int s = 3; s < 6; s++) {
            uint32_t a[4][4];
#pragma unroll
            for (int mt = 0; mt < 4; mt++)
                LDSM_X4(a[mt], h1lda + (uint32_t)(mt * 16 * H1_STRIDE_H * 2 + s * 32));
#pragma unroll
            for (int mt = 0; mt < 4; mt++)
#pragma unroll
                for (int nt = 0; nt < 4; nt++)
                    mma16(acc[mt][nt], a[mt], B2[s][nt]);
        }

        // chunk1 -> next X buffer; issue chunk2 gathers
        enc_store2(el0 + 2, ec, xdstn);
        enc_gather2(el0 + 4, nfx, nfy, tab, ec);

        // ---------------- GEMM2: s = 6..7 -----------------------------------
#pragma unroll
        for (int s = 6; s < 8; s++) {
            uint32_t a[4][4];
#pragma unroll
            for (int mt = 0; mt < 4; mt++)
                LDSM_X4(a[mt], h1lda + (uint32_t)(mt * 16 * H1_STRIDE_H * 2 + s * 32));
#pragma unroll
            for (int mt = 0; mt < 4; mt++)
#pragma unroll
                for (int nt = 0; nt < 4; nt++)
                    mma16(acc[mt][nt], a[mt], B2[s][nt]);
        }

        // ---------------- epilogue: partial relu(H2).w3 per N-group ---------
        {
            float w3a[4], w3b[4];
#pragma unroll
            for (int nt = 0; nt < 4; nt++) {
                w3a[nt] = __ldg(w3 + ng * 32 + nt * 8 + 2 * q);
                w3b[nt] = __ldg(w3 + ng * 32 + nt * 8 + 2 * q + 1);
            }
#pragma unroll
            for (int mt = 0; mt < 4; mt++) {
                float s0 = 0.f, s1 = 0.f;
#pragma unroll
                for (int nt = 0; nt < 4; nt++) {
                    s0 += fmaxf(acc[mt][nt][0], 0.f) * w3a[nt] + fmaxf(acc[mt][nt][1], 0.f) * w3b[nt];
                    s1 += fmaxf(acc[mt][nt][2], 0.f) * w3a[nt] + fmaxf(acc[mt][nt][3], 0.f) * w3b[nt];
                }
                s0 += __shfl_xor_sync(0xffffffffu, s0, 1);
                s0 += __shfl_xor_sync(0xffffffffu, s0, 2);
                s1 += __shfl_xor_sync(0xffffffffu, s1, 1);
                s1 += __shfl_xor_sync(0xffffffffu, s1, 2);
                if (q == 0) {
                    int r0 = mt * 16 + ln4;
                    part[ng * 64 + r0] = s0;
                    part[ng * 64 + r0 + 8] = s1;
                }
            }
        }
        __syncthreads();

        if (tid < 64) {
            float o = (part[tid] + part[64 + tid] + part[128 + tid] + part[192 + tid]) * INV_SCALE;
            out[b * 64 + tid] = o;
        }
        // chunk2 -> next X buffer, then publish for next GEMM1
        enc_store2(el0 + 4, ec, xdstn);
        __syncthreads();
        p ^= 1;
    }
}

extern "C" void kernel_launch(void* const* d_in, const int* in_sizes, int n_in,
                              void* d_out, int out_size) {
    const float* table = nullptr;
    const float* w1 = nullptr;
    const float* w2 = nullptr;
    const float* w3 = nullptr;
    for (int i = 0; i < n_in; i++) {
        switch (in_sizes[i]) {
            case 12 * 1048576 * 4: table = (const float*)d_in[i]; break;
            case 48 * 128:         w1 = (const float*)d_in[i]; break;
            case 128 * 128:        w2 = (const float*)d_in[i]; break;
            case 128:              w3 = (const float*)d_in[i]; break;
            default: break;
        }
    }
    if (!table) table = (const float*)d_in[2];
    if (!w1) w1 = (const float*)d_in[3];
    if (!w2) w2 = (const float*)d_in[4];
    if (!w3) w3 = (const float*)d_in[5];

    cudaFuncSetAttribute(inr_kernel, cudaFuncAttributeMaxDynamicSharedMemorySize, SMEM_BYTES);
    inr_kernel<<<NCTA, 128, SMEM_BYTES>>>((const float4*)table, w1, w2, w3, (float*)d_out);
}